// round 1
// baseline (speedup 1.0000x reference)
#include <cuda_runtime.h>
#include <cuda_bf16.h>

#define MAX_N 50000
#define DD 64

__device__ __align__(16) float g_summed[MAX_N * DD];
__device__ float g_counts[MAX_N];

// ---------- f32x2 packed-math helpers (sm_103a) ----------
__device__ __forceinline__ unsigned long long ffma2(unsigned long long a,
                                                    unsigned long long b,
                                                    unsigned long long c) {
    unsigned long long d;
    asm("fma.rn.f32x2 %0, %1, %2, %3;" : "=l"(d) : "l"(a), "l"(b), "l"(c));
    return d;
}
__device__ __forceinline__ unsigned long long pack2(float lo, float hi) {
    unsigned long long r;
    asm("mov.b64 %0, {%1, %2};" : "=l"(r) : "f"(lo), "f"(hi));
    return r;
}
__device__ __forceinline__ void unpack2(unsigned long long v, float& lo, float& hi) {
    asm("mov.b64 {%0, %1}, %2;" : "=f"(lo), "=f"(hi) : "l"(v));
}

// h2[0..31] += s * wrow[0..63]   (wrow in smem, broadcast across warp)
__device__ __forceinline__ void accum_row(unsigned long long* h2, const float* wrow, float s) {
    unsigned long long s2 = pack2(s, s);
    const ulonglong2* w = (const ulonglong2*)wrow;
#pragma unroll
    for (int j = 0; j < 16; j++) {
        ulonglong2 wv = w[j];
        h2[2 * j]     = ffma2(s2, wv.x, h2[2 * j]);
        h2[2 * j + 1] = ffma2(s2, wv.y, h2[2 * j + 1]);
    }
}

// o2[0..15] += s2 * wrow[0..31]  (half-width output tile)
__device__ __forceinline__ void accum_half(unsigned long long* o2, const float* wrow,
                                           unsigned long long s2) {
    const ulonglong2* w = (const ulonglong2*)wrow;
#pragma unroll
    for (int j = 0; j < 8; j++) {
        ulonglong2 wv = w[j];
        o2[2 * j]     = ffma2(s2, wv.x, o2[2 * j]);
        o2[2 * j + 1] = ffma2(s2, wv.y, o2[2 * j + 1]);
    }
}

// ---------- zero scratch ----------
__global__ void zero_kernel(int n_f4, int n_cnt) {
    int i = blockIdx.x * blockDim.x + threadIdx.x;
    int stride = gridDim.x * blockDim.x;
    float4 z = make_float4(0.f, 0.f, 0.f, 0.f);
    for (int j = i; j < n_f4; j += stride) ((float4*)g_summed)[j] = z;
    for (int j = i; j < n_cnt; j += stride) g_counts[j] = 0.f;
}

// ---------- fused edge MLP + scatter-add ----------
__global__ void __launch_bounds__(128) edge_kernel(
    const float* __restrict__ x, const int* __restrict__ ei,
    const float* __restrict__ ea,
    const float* __restrict__ w1a, const float* __restrict__ b1a,
    const float* __restrict__ w1b, const float* __restrict__ b1b,
    int E) {
    __shared__ __align__(16) float sw1a[128 * 64];  // 32KB
    __shared__ __align__(16) float sw1b[64 * 64];   // 16KB

    for (int i = threadIdx.x; i < 128 * 64 / 4; i += blockDim.x)
        ((float4*)sw1a)[i] = ((const float4*)w1a)[i];
    for (int i = threadIdx.x; i < 64 * 64 / 4; i += blockDim.x)
        ((float4*)sw1b)[i] = ((const float4*)w1b)[i];
    __syncthreads();

    int e = blockIdx.x * blockDim.x + threadIdx.x;
    if (e >= E) return;

    int row = ei[e];
    int col = ei[E + e];

    unsigned long long h2[32];
    const unsigned long long* b1a2 = (const unsigned long long*)b1a;
#pragma unroll
    for (int j = 0; j < 32; j++) h2[j] = __ldg(&b1a2[j]);

    const float4* xin = (const float4*)(x + (long long)row * DD);
    const float4* eap = (const float4*)(ea + (long long)e * DD);

    // layer 1, k = 0..63 from x[row]
#pragma unroll 2
    for (int k4 = 0; k4 < 16; k4++) {
        float4 v = __ldg(&xin[k4]);
        accum_row(h2, sw1a + (4 * k4 + 0) * 64, v.x);
        accum_row(h2, sw1a + (4 * k4 + 1) * 64, v.y);
        accum_row(h2, sw1a + (4 * k4 + 2) * 64, v.z);
        accum_row(h2, sw1a + (4 * k4 + 3) * 64, v.w);
    }
    // layer 1, k = 64..127 from edge_attr[e]
#pragma unroll 2
    for (int k4 = 0; k4 < 16; k4++) {
        float4 v = __ldg(&eap[k4]);
        accum_row(h2, sw1a + (64 + 4 * k4 + 0) * 64, v.x);
        accum_row(h2, sw1a + (64 + 4 * k4 + 1) * 64, v.y);
        accum_row(h2, sw1a + (64 + 4 * k4 + 2) * 64, v.z);
        accum_row(h2, sw1a + (64 + 4 * k4 + 3) * 64, v.w);
    }

    // ReLU
#pragma unroll
    for (int j = 0; j < 32; j++) {
        float a, b;
        unpack2(h2[j], a, b);
        h2[j] = pack2(fmaxf(a, 0.f), fmaxf(b, 0.f));
    }

    // layer 2 in two 32-column halves, then vector scatter-add
    float* sumbase = g_summed + (long long)col * DD;
    const unsigned long long* b1b2 = (const unsigned long long*)b1b;
#pragma unroll 1
    for (int half = 0; half < 2; half++) {
        unsigned long long o2[16];
#pragma unroll
        for (int j = 0; j < 16; j++) o2[j] = __ldg(&b1b2[half * 16 + j]);
#pragma unroll 2
        for (int i2 = 0; i2 < 32; i2++) {
            float a, b;
            unpack2(h2[i2], a, b);
            accum_half(o2, sw1b + (2 * i2) * 64 + half * 32, pack2(a, a));
            accum_half(o2, sw1b + (2 * i2 + 1) * 64 + half * 32, pack2(b, b));
        }
        // biases b1b are added once per edge but divided by count later.
        // Reference adds bias once per edge BEFORE mean -> mean(h+b) = mean(h)+b. OK.
#pragma unroll
        for (int j4 = 0; j4 < 8; j4++) {
            float f0, f1, f2, f3;
            unpack2(o2[2 * j4], f0, f1);
            unpack2(o2[2 * j4 + 1], f2, f3);
            asm volatile("red.global.add.v4.f32 [%0], {%1,%2,%3,%4};"
                         :: "l"(sumbase + half * 32 + j4 * 4),
                            "f"(f0), "f"(f1), "f"(f2), "f"(f3)
                         : "memory");
        }
    }
    atomicAdd(&g_counts[col], 1.0f);
}

// ---------- fused node MLP ----------
__global__ void __launch_bounds__(128) node_kernel(
    const float* __restrict__ x,
    const float* __restrict__ w2a, const float* __restrict__ b2a,
    const float* __restrict__ w2b, const float* __restrict__ b2b,
    float* __restrict__ out, int N) {
    __shared__ __align__(16) float sw2a[128 * 64];
    __shared__ __align__(16) float sw2b[64 * 64];

    for (int i = threadIdx.x; i < 128 * 64 / 4; i += blockDim.x)
        ((float4*)sw2a)[i] = ((const float4*)w2a)[i];
    for (int i = threadIdx.x; i < 64 * 64 / 4; i += blockDim.x)
        ((float4*)sw2b)[i] = ((const float4*)w2b)[i];
    __syncthreads();

    int n = blockIdx.x * blockDim.x + threadIdx.x;
    if (n >= N) return;

    unsigned long long h2[32];
    const unsigned long long* b2a2 = (const unsigned long long*)b2a;
#pragma unroll
    for (int j = 0; j < 32; j++) h2[j] = __ldg(&b2a2[j]);

    const float4* xin = (const float4*)(x + (long long)n * DD);
#pragma unroll 2
    for (int k4 = 0; k4 < 16; k4++) {
        float4 v = __ldg(&xin[k4]);
        accum_row(h2, sw2a + (4 * k4 + 0) * 64, v.x);
        accum_row(h2, sw2a + (4 * k4 + 1) * 64, v.y);
        accum_row(h2, sw2a + (4 * k4 + 2) * 64, v.z);
        accum_row(h2, sw2a + (4 * k4 + 3) * 64, v.w);
    }
    float cnt = g_counts[n];
    float inv = 1.0f / fmaxf(cnt, 1.0f);
    const float4* ag = (const float4*)(g_summed + (long long)n * DD);
#pragma unroll 2
    for (int k4 = 0; k4 < 16; k4++) {
        float4 v = ag[k4];
        accum_row(h2, sw2a + (64 + 4 * k4 + 0) * 64, v.x * inv);
        accum_row(h2, sw2a + (64 + 4 * k4 + 1) * 64, v.y * inv);
        accum_row(h2, sw2a + (64 + 4 * k4 + 2) * 64, v.z * inv);
        accum_row(h2, sw2a + (64 + 4 * k4 + 3) * 64, v.w * inv);
    }

#pragma unroll
    for (int j = 0; j < 32; j++) {
        float a, b;
        unpack2(h2[j], a, b);
        h2[j] = pack2(fmaxf(a, 0.f), fmaxf(b, 0.f));
    }

    float* outp = out + (long long)n * DD;
    const unsigned long long* b2b2 = (const unsigned long long*)b2b;
#pragma unroll 1
    for (int half = 0; half < 2; half++) {
        unsigned long long o2[16];
#pragma unroll
        for (int j = 0; j < 16; j++) o2[j] = __ldg(&b2b2[half * 16 + j]);
#pragma unroll 2
        for (int i2 = 0; i2 < 32; i2++) {
            float a, b;
            unpack2(h2[i2], a, b);
            accum_half(o2, sw2b + (2 * i2) * 64 + half * 32, pack2(a, a));
            accum_half(o2, sw2b + (2 * i2 + 1) * 64 + half * 32, pack2(b, b));
        }
#pragma unroll
        for (int j4 = 0; j4 < 8; j4++) {
            float f0, f1, f2, f3;
            unpack2(o2[2 * j4], f0, f1);
            unpack2(o2[2 * j4 + 1], f2, f3);
            ((float4*)(outp + half * 32))[j4] = make_float4(f0, f1, f2, f3);
        }
    }
}

extern "C" void kernel_launch(void* const* d_in, const int* in_sizes, int n_in,
                              void* d_out, int out_size) {
    const float* x   = (const float*)d_in[0];
    const int*   ei  = (const int*)d_in[1];
    const float* ea  = (const float*)d_in[2];
    // d_in[3] = u, d_in[4] = batch (unused by reference output)
    const float* w1a = (const float*)d_in[5];
    const float* b1a = (const float*)d_in[6];
    const float* w1b = (const float*)d_in[7];
    const float* b1b = (const float*)d_in[8];
    const float* w2a = (const float*)d_in[9];
    const float* b2a = (const float*)d_in[10];
    const float* w2b = (const float*)d_in[11];
    const float* b2b = (const float*)d_in[12];
    float* out = (float*)d_out;

    int N = in_sizes[0] / DD;
    int E = in_sizes[2] / DD;

    zero_kernel<<<1024, 256>>>(N * DD / 4, N);
    edge_kernel<<<(E + 127) / 128, 128>>>(x, ei, ea, w1a, b1a, w1b, b1b, E);
    node_kernel<<<(N + 127) / 128, 128>>>(x, w2a, b2a, w2b, b2b, out, N);
}

// round 2
// speedup vs baseline: 1.7066x; 1.7066x over previous
#include <cuda_runtime.h>
#include <cuda_bf16.h>

#define MAX_N 50016
#define DD 64

__device__ __align__(16) float g_summed[MAX_N * DD];
__device__ float g_counts[MAX_N];
__device__ __align__(16) float g_hx[MAX_N * DD];   // x @ w1a[0:64] + b1a
__device__ __align__(16) float g_hx2[MAX_N * DD];  // x @ w2a[0:64] + b2a

typedef unsigned long long ull;

// ---------- f32x2 packed-math helpers (sm_103a) ----------
__device__ __forceinline__ ull ffma2(ull a, ull b, ull c) {
    ull d;
    asm("fma.rn.f32x2 %0, %1, %2, %3;" : "=l"(d) : "l"(a), "l"(b), "l"(c));
    return d;
}
__device__ __forceinline__ ull fadd2(ull a, ull b) {
    ull d;
    asm("add.rn.f32x2 %0, %1, %2;" : "=l"(d) : "l"(a), "l"(b));
    return d;
}
__device__ __forceinline__ ull pack2(float lo, float hi) {
    ull r;
    asm("mov.b64 %0, {%1, %2};" : "=l"(r) : "f"(lo), "f"(hi));
    return r;
}
__device__ __forceinline__ void unpack2(ull v, float& lo, float& hi) {
    asm("mov.b64 {%0, %1}, %2;" : "=f"(lo), "=f"(hi) : "l"(v));
}
__device__ __forceinline__ ull relu2(ull v) {
    float a, b;
    unpack2(v, a, b);
    return pack2(fmaxf(a, 0.f), fmaxf(b, 0.f));
}

// h2[0..31] += s * wrow[0..63] (wrow smem, broadcast), used by hx/node kernels
__device__ __forceinline__ void accum_row(ull* h2, const float* wrow, float s) {
    ull s2 = pack2(s, s);
    const ulonglong2* w = (const ulonglong2*)wrow;
#pragma unroll
    for (int j = 0; j < 16; j++) {
        ulonglong2 wv = w[j];
        h2[2 * j]     = ffma2(s2, wv.x, h2[2 * j]);
        h2[2 * j + 1] = ffma2(s2, wv.y, h2[2 * j + 1]);
    }
}
__device__ __forceinline__ void accum_half(ull* o2, const float* wrow, ull s2) {
    const ulonglong2* w = (const ulonglong2*)wrow;
#pragma unroll
    for (int j = 0; j < 8; j++) {
        ulonglong2 wv = w[j];
        o2[2 * j]     = ffma2(s2, wv.x, o2[2 * j]);
        o2[2 * j + 1] = ffma2(s2, wv.y, o2[2 * j + 1]);
    }
}

// ---------- zero scratch (split in two for ncu launch alignment) ----------
__global__ void zero_summed(int n_f4) {
    int i = blockIdx.x * blockDim.x + threadIdx.x;
    int stride = gridDim.x * blockDim.x;
    float4 z = make_float4(0.f, 0.f, 0.f, 0.f);
    for (int j = i; j < n_f4; j += stride) ((float4*)g_summed)[j] = z;
}
__global__ void zero_counts(int n) {
    int i = blockIdx.x * blockDim.x + threadIdx.x;
    if (i < n) g_counts[i] = 0.f;
}

// ---------- per-node precompute: hx = x@w1a_top + b1a, hx2 = x@w2a_top + b2a ----------
__global__ void __launch_bounds__(128) hx_kernel(
    const float* __restrict__ x,
    const float* __restrict__ w1a, const float* __restrict__ b1a,
    const float* __restrict__ w2a, const float* __restrict__ b2a,
    int N) {
    __shared__ __align__(16) float sw[64 * 64];
    int which = blockIdx.y;  // 0 -> hx (w1a), 1 -> hx2 (w2a)
    const float* w = which ? w2a : w1a;  // top 64 rows (rows 0..63 of the 128-row matrix)
    const float* b = which ? b2a : b1a;
    for (int i = threadIdx.x; i < 64 * 64 / 4; i += blockDim.x)
        ((float4*)sw)[i] = ((const float4*)w)[i];
    __syncthreads();

    int n = blockIdx.x * blockDim.x + threadIdx.x;
    if (n >= N) return;

    ull h[32];
    const ull* b2 = (const ull*)b;
#pragma unroll
    for (int j = 0; j < 32; j++) h[j] = __ldg(&b2[j]);

    const float4* xin = (const float4*)(x + (size_t)n * DD);
#pragma unroll 2
    for (int k4 = 0; k4 < 16; k4++) {
        float4 v = __ldg(&xin[k4]);
        accum_row(h, sw + (4 * k4 + 0) * 64, v.x);
        accum_row(h, sw + (4 * k4 + 1) * 64, v.y);
        accum_row(h, sw + (4 * k4 + 2) * 64, v.z);
        accum_row(h, sw + (4 * k4 + 3) * 64, v.w);
    }
    float* dst = (which ? g_hx2 : g_hx) + (size_t)n * DD;
#pragma unroll
    for (int j = 0; j < 32; j++) ((ull*)dst)[j] = h[j];
}

// ---------- fused edge MLP + scatter-add ----------
// Thread layout: tid = pid*2 + c; pair (c=0,1) covers 2 edges (e0,e1) full width.
// Each lane: layer1 accumulates its 32-column half for both edges (4 ffma2 per LDS.128);
// layer2 computes partials over its 32 hidden values, shuffle-combined with partner.
__global__ void __launch_bounds__(128) edge_kernel(
    const int* __restrict__ ei, const float* __restrict__ ea,
    const float* __restrict__ w1a,  // uses rows 64..127
    const float* __restrict__ w1b, const float* __restrict__ b1b,
    int E) {
    __shared__ __align__(16) float sw1[64 * 68];      // w1a bottom, col-half pad (+4 at col>=32)
    __shared__ __align__(16) float sw2[64 * 68 + 8];  // w1b, row-half pad (+4 at row>=32)

    for (int idx = threadIdx.x; idx < 64 * 64; idx += blockDim.x) {
        int k = idx >> 6, col = idx & 63;
        sw1[k * 68 + col + (col >= 32 ? 4 : 0)] = w1a[(64 + k) * 64 + col];
        sw2[k * 68 + (k >= 32 ? 4 : 0) + col] = w1b[idx];
    }
    __syncthreads();

    int t = threadIdx.x;
    int pid = t >> 1, c = t & 1;
    long long e0 = (long long)blockIdx.x * 128 + pid * 2;
    long long e1 = e0 + 1;
    if (e0 >= E) return;
    bool h1v = (e1 < E);

    int row0 = ei[e0];
    int row1 = h1v ? ei[e1] : 0;
    int col0 = ei[E + e0];
    int col1 = h1v ? ei[E + e1] : 0;

    // init h halves from precomputed hx (includes b1a)
    ull h0[16], h1[16];
    const ull* hxp0 = (const ull*)(g_hx + (size_t)row0 * DD + c * 32);
    const ull* hxp1 = (const ull*)(g_hx + (size_t)row1 * DD + c * 32);
#pragma unroll
    for (int j = 0; j < 16; j++) {
        h0[j] = __ldg(&hxp0[j]);
        h1[j] = h1v ? __ldg(&hxp1[j]) : 0ULL;
    }

    // layer 1: += ea[e] @ w1a_bot  (32-col half per lane, both edges)
    const float4* a0p = (const float4*)(ea + (size_t)e0 * DD);
    const float4* a1p = (const float4*)(ea + (size_t)e1 * DD);
    const float* swc = sw1 + c * 36;
#pragma unroll 2
    for (int k4 = 0; k4 < 16; k4++) {
        float4 a0 = __ldg(&a0p[k4]);
        float4 a1 = h1v ? __ldg(&a1p[k4]) : make_float4(0.f, 0.f, 0.f, 0.f);
        float s0[4] = {a0.x, a0.y, a0.z, a0.w};
        float s1[4] = {a1.x, a1.y, a1.z, a1.w};
#pragma unroll
        for (int kk = 0; kk < 4; kk++) {
            const ulonglong2* w = (const ulonglong2*)(swc + (k4 * 4 + kk) * 68);
            ull p0 = pack2(s0[kk], s0[kk]);
            ull p1 = pack2(s1[kk], s1[kk]);
#pragma unroll
            for (int q = 0; q < 8; q++) {
                ulonglong2 wv = w[q];
                h0[2 * q]     = ffma2(p0, wv.x, h0[2 * q]);
                h0[2 * q + 1] = ffma2(p0, wv.y, h0[2 * q + 1]);
                h1[2 * q]     = ffma2(p1, wv.x, h1[2 * q]);
                h1[2 * q + 1] = ffma2(p1, wv.y, h1[2 * q + 1]);
            }
        }
    }

    // ReLU
#pragma unroll
    for (int j = 0; j < 16; j++) {
        h0[j] = relu2(h0[j]);
        h1[j] = relu2(h1[j]);
    }

    // counts
    if (c == 0) {
        atomicAdd(&g_counts[col0], 1.0f);
        if (h1v) atomicAdd(&g_counts[col1], 1.0f);
    }

    // layer 2 in four 16-column quarter passes
    float* dst0 = g_summed + (size_t)col0 * DD;
    float* dst1 = g_summed + (size_t)col1 * DD;
    unsigned mask = __activemask();
#pragma unroll 1
    for (int H = 0; H < 4; H++) {
        ull o0[8], o1[8];
        const ull* bb = (const ull*)(b1b + H * 16);
#pragma unroll
        for (int q = 0; q < 8; q++) {
            ull bq = (c == 0) ? __ldg(&bb[q]) : 0ULL;
            o0[q] = bq;
            o1[q] = bq;
        }
        // partials over my 32 hidden values (absolute rows c*32 + 2j, +1)
        const float* sw2c = sw2 + (c ? (32 * 68 + 4) : 0) + H * 16;
#pragma unroll
        for (int j = 0; j < 16; j++) {
            float a0, a1;
            unpack2(h0[j], a0, a1);
            float b0, b1f;
            unpack2(h1[j], b0, b1f);
            const ulonglong2* wr0 = (const ulonglong2*)(sw2c + (2 * j) * 68);
            const ulonglong2* wr1 = (const ulonglong2*)(sw2c + (2 * j + 1) * 68);
            ull pa0 = pack2(a0, a0), pa1 = pack2(a1, a1);
            ull pb0 = pack2(b0, b0), pb1 = pack2(b1f, b1f);
#pragma unroll
            for (int q = 0; q < 4; q++) {
                ulonglong2 w0 = wr0[q];
                o0[2 * q]     = ffma2(pa0, w0.x, o0[2 * q]);
                o0[2 * q + 1] = ffma2(pa0, w0.y, o0[2 * q + 1]);
                o1[2 * q]     = ffma2(pb0, w0.x, o1[2 * q]);
                o1[2 * q + 1] = ffma2(pb0, w0.y, o1[2 * q + 1]);
            }
#pragma unroll
            for (int q = 0; q < 4; q++) {
                ulonglong2 w1v = wr1[q];
                o0[2 * q]     = ffma2(pa1, w1v.x, o0[2 * q]);
                o0[2 * q + 1] = ffma2(pa1, w1v.y, o0[2 * q + 1]);
                o1[2 * q]     = ffma2(pb1, w1v.x, o1[2 * q]);
                o1[2 * q + 1] = ffma2(pb1, w1v.y, o1[2 * q + 1]);
            }
        }
        // combine partner's half-contribution
#pragma unroll
        for (int q = 0; q < 8; q++) {
            o0[q] = fadd2(o0[q], __shfl_xor_sync(mask, o0[q], 1));
            o1[q] = fadd2(o1[q], __shfl_xor_sync(mask, o1[q], 1));
        }
        // lane c writes edge e_c
        ull* oo = (c == 0) ? o0 : o1;
        float* dst = ((c == 0) ? dst0 : dst1) + H * 16;
        if (c == 0 || h1v) {
#pragma unroll
            for (int q = 0; q < 4; q++) {
                float f0, f1, f2, f3;
                unpack2(oo[2 * q], f0, f1);
                unpack2(oo[2 * q + 1], f2, f3);
                asm volatile("red.global.add.v4.f32 [%0], {%1,%2,%3,%4};"
                             :: "l"(dst + q * 4), "f"(f0), "f"(f1), "f"(f2), "f"(f3)
                             : "memory");
            }
        }
    }
}

// ---------- fused node MLP (uses precomputed hx2) ----------
__global__ void __launch_bounds__(128) node_kernel(
    const float* __restrict__ w2a,  // uses rows 64..127
    const float* __restrict__ w2b, const float* __restrict__ b2b,
    float* __restrict__ out, int N) {
    __shared__ __align__(16) float sw2a[64 * 64];  // bottom rows only
    __shared__ __align__(16) float sw2b[64 * 64];

    for (int i = threadIdx.x; i < 64 * 64 / 4; i += blockDim.x) {
        ((float4*)sw2a)[i] = ((const float4*)(w2a + 64 * 64))[i];
        ((float4*)sw2b)[i] = ((const float4*)w2b)[i];
    }
    __syncthreads();

    int n = blockIdx.x * blockDim.x + threadIdx.x;
    if (n >= N) return;

    ull h2[32];
    const ull* hxp = (const ull*)(g_hx2 + (size_t)n * DD);
#pragma unroll
    for (int j = 0; j < 32; j++) h2[j] = __ldg(&hxp[j]);

    float cnt = g_counts[n];
    float inv = 1.0f / fmaxf(cnt, 1.0f);
    const float4* ag = (const float4*)(g_summed + (size_t)n * DD);
#pragma unroll 2
    for (int k4 = 0; k4 < 16; k4++) {
        float4 v = ag[k4];
        accum_row(h2, sw2a + (4 * k4 + 0) * 64, v.x * inv);
        accum_row(h2, sw2a + (4 * k4 + 1) * 64, v.y * inv);
        accum_row(h2, sw2a + (4 * k4 + 2) * 64, v.z * inv);
        accum_row(h2, sw2a + (4 * k4 + 3) * 64, v.w * inv);
    }

#pragma unroll
    for (int j = 0; j < 32; j++) h2[j] = relu2(h2[j]);

    float* outp = out + (size_t)n * DD;
    const ull* b2b2 = (const ull*)b2b;
#pragma unroll 1
    for (int half = 0; half < 2; half++) {
        ull o2[16];
#pragma unroll
        for (int j = 0; j < 16; j++) o2[j] = __ldg(&b2b2[half * 16 + j]);
#pragma unroll 2
        for (int i2 = 0; i2 < 32; i2++) {
            float a, b;
            unpack2(h2[i2], a, b);
            accum_half(o2, sw2b + (2 * i2) * 64 + half * 32, pack2(a, a));
            accum_half(o2, sw2b + (2 * i2 + 1) * 64 + half * 32, pack2(b, b));
        }
#pragma unroll
        for (int j4 = 0; j4 < 8; j4++) {
            float f0, f1, f2, f3;
            unpack2(o2[2 * j4], f0, f1);
            unpack2(o2[2 * j4 + 1], f2, f3);
            ((float4*)(outp + half * 32))[j4] = make_float4(f0, f1, f2, f3);
        }
    }
}

extern "C" void kernel_launch(void* const* d_in, const int* in_sizes, int n_in,
                              void* d_out, int out_size) {
    const float* x   = (const float*)d_in[0];
    const int*   ei  = (const int*)d_in[1];
    const float* ea  = (const float*)d_in[2];
    // d_in[3] = u, d_in[4] = batch (unused by reference output)
    const float* w1a = (const float*)d_in[5];
    const float* b1a = (const float*)d_in[6];
    const float* w1b = (const float*)d_in[7];
    const float* b1b = (const float*)d_in[8];
    const float* w2a = (const float*)d_in[9];
    const float* b2a = (const float*)d_in[10];
    const float* w2b = (const float*)d_in[11];
    const float* b2b = (const float*)d_in[12];
    float* out = (float*)d_out;

    int N = in_sizes[0] / DD;
    int E = in_sizes[2] / DD;

    zero_summed<<<512, 256>>>(N * DD / 4);
    zero_counts<<<(N + 255) / 256, 256>>>(N);
    dim3 hxgrid((N + 127) / 128, 2);
    hx_kernel<<<hxgrid, 128>>>(x, w1a, b1a, w2a, b2a, N);
    edge_kernel<<<(E + 127) / 128, 128>>>(ei, ea, w1a, w1b, b1b, E);
    node_kernel<<<(N + 127) / 128, 128>>>(w2a, w2b, b2b, out, N);
}

// round 3
// speedup vs baseline: 1.7081x; 1.0008x over previous
#include <cuda_runtime.h>
#include <cuda_bf16.h>

#define MAX_N 50016
#define DD 64

__device__ __align__(16) float g_summed[MAX_N * DD];
__device__ float g_counts[MAX_N];
__device__ __align__(16) float g_hx[MAX_N * DD];   // x @ w1a[0:64] + b1a
__device__ __align__(16) float g_hx2[MAX_N * DD];  // x @ w2a[0:64] + b2a

typedef unsigned long long ull;

// ---------- f32x2 packed-math helpers (sm_103a) ----------
__device__ __forceinline__ ull ffma2(ull a, ull b, ull c) {
    ull d;
    asm("fma.rn.f32x2 %0, %1, %2, %3;" : "=l"(d) : "l"(a), "l"(b), "l"(c));
    return d;
}
__device__ __forceinline__ ull fadd2(ull a, ull b) {
    ull d;
    asm("add.rn.f32x2 %0, %1, %2;" : "=l"(d) : "l"(a), "l"(b));
    return d;
}
__device__ __forceinline__ ull pack2(float lo, float hi) {
    ull r;
    asm("mov.b64 %0, {%1, %2};" : "=l"(r) : "f"(lo), "f"(hi));
    return r;
}
__device__ __forceinline__ void unpack2(ull v, float& lo, float& hi) {
    asm("mov.b64 {%0, %1}, %2;" : "=f"(lo), "=f"(hi) : "l"(v));
}
__device__ __forceinline__ ull relu2(ull v) {
    float a, b;
    unpack2(v, a, b);
    return pack2(fmaxf(a, 0.f), fmaxf(b, 0.f));
}

// h2[0..31] += s * wrow[0..63] (wrow smem, broadcast), used by hx/node kernels
__device__ __forceinline__ void accum_row(ull* h2, const float* wrow, float s) {
    ull s2 = pack2(s, s);
    const ulonglong2* w = (const ulonglong2*)wrow;
#pragma unroll
    for (int j = 0; j < 16; j++) {
        ulonglong2 wv = w[j];
        h2[2 * j]     = ffma2(s2, wv.x, h2[2 * j]);
        h2[2 * j + 1] = ffma2(s2, wv.y, h2[2 * j + 1]);
    }
}
__device__ __forceinline__ void accum_half(ull* o2, const float* wrow, ull s2) {
    const ulonglong2* w = (const ulonglong2*)wrow;
#pragma unroll
    for (int j = 0; j < 8; j++) {
        ulonglong2 wv = w[j];
        o2[2 * j]     = ffma2(s2, wv.x, o2[2 * j]);
        o2[2 * j + 1] = ffma2(s2, wv.y, o2[2 * j + 1]);
    }
}

// ---------- zero scratch (split in two for ncu launch alignment) ----------
__global__ void zero_summed(int n_f4) {
    int i = blockIdx.x * blockDim.x + threadIdx.x;
    int stride = gridDim.x * blockDim.x;
    float4 z = make_float4(0.f, 0.f, 0.f, 0.f);
    for (int j = i; j < n_f4; j += stride) ((float4*)g_summed)[j] = z;
}
__global__ void zero_counts(int n) {
    int i = blockIdx.x * blockDim.x + threadIdx.x;
    if (i < n) g_counts[i] = 0.f;
}

// ---------- per-node precompute: hx = x@w1a_top + b1a, hx2 = x@w2a_top + b2a ----------
__global__ void __launch_bounds__(128) hx_kernel(
    const float* __restrict__ x,
    const float* __restrict__ w1a, const float* __restrict__ b1a,
    const float* __restrict__ w2a, const float* __restrict__ b2a,
    int N) {
    __shared__ __align__(16) float sw[64 * 64];
    int which = blockIdx.y;  // 0 -> hx (w1a), 1 -> hx2 (w2a)
    const float* w = which ? w2a : w1a;  // top 64 rows (rows 0..63 of the 128-row matrix)
    const float* b = which ? b2a : b1a;
    for (int i = threadIdx.x; i < 64 * 64 / 4; i += blockDim.x)
        ((float4*)sw)[i] = ((const float4*)w)[i];
    __syncthreads();

    int n = blockIdx.x * blockDim.x + threadIdx.x;
    if (n >= N) return;

    ull h[32];
    const ull* b2 = (const ull*)b;
#pragma unroll
    for (int j = 0; j < 32; j++) h[j] = __ldg(&b2[j]);

    const float4* xin = (const float4*)(x + (size_t)n * DD);
#pragma unroll 2
    for (int k4 = 0; k4 < 16; k4++) {
        float4 v = __ldg(&xin[k4]);
        accum_row(h, sw + (4 * k4 + 0) * 64, v.x);
        accum_row(h, sw + (4 * k4 + 1) * 64, v.y);
        accum_row(h, sw + (4 * k4 + 2) * 64, v.z);
        accum_row(h, sw + (4 * k4 + 3) * 64, v.w);
    }
    float* dst = (which ? g_hx2 : g_hx) + (size_t)n * DD;
#pragma unroll
    for (int j = 0; j < 32; j++) ((ull*)dst)[j] = h[j];
}

// ---------- fused edge MLP + scatter-add ----------
// Thread layout: tid = pid*2 + c; pair (c=0,1) covers 2 edges (e0,e1) full width.
// Each lane: layer1 accumulates its 32-column half for both edges (4 ffma2 per LDS.128);
// layer2 computes partials over its 32 hidden values, shuffle-combined with partner.
__global__ void __launch_bounds__(128) edge_kernel(
    const int* __restrict__ ei, const float* __restrict__ ea,
    const float* __restrict__ w1a,  // uses rows 64..127
    const float* __restrict__ w1b, const float* __restrict__ b1b,
    int E) {
    __shared__ __align__(16) float sw1[64 * 68];      // w1a bottom, col-half pad (+4 at col>=32)
    __shared__ __align__(16) float sw2[64 * 68 + 8];  // w1b, row-half pad (+4 at row>=32)

    for (int idx = threadIdx.x; idx < 64 * 64; idx += blockDim.x) {
        int k = idx >> 6, col = idx & 63;
        sw1[k * 68 + col + (col >= 32 ? 4 : 0)] = w1a[(64 + k) * 64 + col];
        sw2[k * 68 + (k >= 32 ? 4 : 0) + col] = w1b[idx];
    }
    __syncthreads();

    int t = threadIdx.x;
    int pid = t >> 1, c = t & 1;
    long long e0 = (long long)blockIdx.x * 128 + pid * 2;
    long long e1 = e0 + 1;
    if (e0 >= E) return;
    bool h1v = (e1 < E);

    int row0 = ei[e0];
    int row1 = h1v ? ei[e1] : 0;
    int col0 = ei[E + e0];
    int col1 = h1v ? ei[E + e1] : 0;

    // init h halves from precomputed hx (includes b1a)
    ull h0[16], h1[16];
    const ull* hxp0 = (const ull*)(g_hx + (size_t)row0 * DD + c * 32);
    const ull* hxp1 = (const ull*)(g_hx + (size_t)row1 * DD + c * 32);
#pragma unroll
    for (int j = 0; j < 16; j++) {
        h0[j] = __ldg(&hxp0[j]);
        h1[j] = h1v ? __ldg(&hxp1[j]) : 0ULL;
    }

    // layer 1: += ea[e] @ w1a_bot  (32-col half per lane, both edges)
    const float4* a0p = (const float4*)(ea + (size_t)e0 * DD);
    const float4* a1p = (const float4*)(ea + (size_t)e1 * DD);
    const float* swc = sw1 + c * 36;
#pragma unroll 2
    for (int k4 = 0; k4 < 16; k4++) {
        float4 a0 = __ldg(&a0p[k4]);
        float4 a1 = h1v ? __ldg(&a1p[k4]) : make_float4(0.f, 0.f, 0.f, 0.f);
        float s0[4] = {a0.x, a0.y, a0.z, a0.w};
        float s1[4] = {a1.x, a1.y, a1.z, a1.w};
#pragma unroll
        for (int kk = 0; kk < 4; kk++) {
            const ulonglong2* w = (const ulonglong2*)(swc + (k4 * 4 + kk) * 68);
            ull p0 = pack2(s0[kk], s0[kk]);
            ull p1 = pack2(s1[kk], s1[kk]);
#pragma unroll
            for (int q = 0; q < 8; q++) {
                ulonglong2 wv = w[q];
                h0[2 * q]     = ffma2(p0, wv.x, h0[2 * q]);
                h0[2 * q + 1] = ffma2(p0, wv.y, h0[2 * q + 1]);
                h1[2 * q]     = ffma2(p1, wv.x, h1[2 * q]);
                h1[2 * q + 1] = ffma2(p1, wv.y, h1[2 * q + 1]);
            }
        }
    }

    // ReLU
#pragma unroll
    for (int j = 0; j < 16; j++) {
        h0[j] = relu2(h0[j]);
        h1[j] = relu2(h1[j]);
    }

    // counts
    if (c == 0) {
        atomicAdd(&g_counts[col0], 1.0f);
        if (h1v) atomicAdd(&g_counts[col1], 1.0f);
    }

    // layer 2 in four 16-column quarter passes
    float* dst0 = g_summed + (size_t)col0 * DD;
    float* dst1 = g_summed + (size_t)col1 * DD;
    unsigned mask = __activemask();
#pragma unroll 1
    for (int H = 0; H < 4; H++) {
        ull o0[8], o1[8];
        const ull* bb = (const ull*)(b1b + H * 16);
#pragma unroll
        for (int q = 0; q < 8; q++) {
            ull bq = (c == 0) ? __ldg(&bb[q]) : 0ULL;
            o0[q] = bq;
            o1[q] = bq;
        }
        // partials over my 32 hidden values (absolute rows c*32 + 2j, +1)
        const float* sw2c = sw2 + (c ? (32 * 68 + 4) : 0) + H * 16;
#pragma unroll
        for (int j = 0; j < 16; j++) {
            float a0, a1;
            unpack2(h0[j], a0, a1);
            float b0, b1f;
            unpack2(h1[j], b0, b1f);
            const ulonglong2* wr0 = (const ulonglong2*)(sw2c + (2 * j) * 68);
            const ulonglong2* wr1 = (const ulonglong2*)(sw2c + (2 * j + 1) * 68);
            ull pa0 = pack2(a0, a0), pa1 = pack2(a1, a1);
            ull pb0 = pack2(b0, b0), pb1 = pack2(b1f, b1f);
#pragma unroll
            for (int q = 0; q < 4; q++) {
                ulonglong2 w0 = wr0[q];
                o0[2 * q]     = ffma2(pa0, w0.x, o0[2 * q]);
                o0[2 * q + 1] = ffma2(pa0, w0.y, o0[2 * q + 1]);
                o1[2 * q]     = ffma2(pb0, w0.x, o1[2 * q]);
                o1[2 * q + 1] = ffma2(pb0, w0.y, o1[2 * q + 1]);
            }
#pragma unroll
            for (int q = 0; q < 4; q++) {
                ulonglong2 w1v = wr1[q];
                o0[2 * q]     = ffma2(pa1, w1v.x, o0[2 * q]);
                o0[2 * q + 1] = ffma2(pa1, w1v.y, o0[2 * q + 1]);
                o1[2 * q]     = ffma2(pb1, w1v.x, o1[2 * q]);
                o1[2 * q + 1] = ffma2(pb1, w1v.y, o1[2 * q + 1]);
            }
        }
        // combine partner's half-contribution
#pragma unroll
        for (int q = 0; q < 8; q++) {
            o0[q] = fadd2(o0[q], __shfl_xor_sync(mask, o0[q], 1));
            o1[q] = fadd2(o1[q], __shfl_xor_sync(mask, o1[q], 1));
        }
        // lane c writes edge e_c
        ull* oo = (c == 0) ? o0 : o1;
        float* dst = ((c == 0) ? dst0 : dst1) + H * 16;
        if (c == 0 || h1v) {
#pragma unroll
            for (int q = 0; q < 4; q++) {
                float f0, f1, f2, f3;
                unpack2(oo[2 * q], f0, f1);
                unpack2(oo[2 * q + 1], f2, f3);
                asm volatile("red.global.add.v4.f32 [%0], {%1,%2,%3,%4};"
                             :: "l"(dst + q * 4), "f"(f0), "f"(f1), "f"(f2), "f"(f3)
                             : "memory");
            }
        }
    }
}

// ---------- fused node MLP (uses precomputed hx2) ----------
__global__ void __launch_bounds__(128) node_kernel(
    const float* __restrict__ w2a,  // uses rows 64..127
    const float* __restrict__ w2b, const float* __restrict__ b2b,
    float* __restrict__ out, int N) {
    __shared__ __align__(16) float sw2a[64 * 64];  // bottom rows only
    __shared__ __align__(16) float sw2b[64 * 64];

    for (int i = threadIdx.x; i < 64 * 64 / 4; i += blockDim.x) {
        ((float4*)sw2a)[i] = ((const float4*)(w2a + 64 * 64))[i];
        ((float4*)sw2b)[i] = ((const float4*)w2b)[i];
    }
    __syncthreads();

    int n = blockIdx.x * blockDim.x + threadIdx.x;
    if (n >= N) return;

    ull h2[32];
    const ull* hxp = (const ull*)(g_hx2 + (size_t)n * DD);
#pragma unroll
    for (int j = 0; j < 32; j++) h2[j] = __ldg(&hxp[j]);

    float cnt = g_counts[n];
    float inv = 1.0f / fmaxf(cnt, 1.0f);
    const float4* ag = (const float4*)(g_summed + (size_t)n * DD);
#pragma unroll 2
    for (int k4 = 0; k4 < 16; k4++) {
        float4 v = ag[k4];
        accum_row(h2, sw2a + (4 * k4 + 0) * 64, v.x * inv);
        accum_row(h2, sw2a + (4 * k4 + 1) * 64, v.y * inv);
        accum_row(h2, sw2a + (4 * k4 + 2) * 64, v.z * inv);
        accum_row(h2, sw2a + (4 * k4 + 3) * 64, v.w * inv);
    }

#pragma unroll
    for (int j = 0; j < 32; j++) h2[j] = relu2(h2[j]);

    float* outp = out + (size_t)n * DD;
    const ull* b2b2 = (const ull*)b2b;
#pragma unroll 1
    for (int half = 0; half < 2; half++) {
        ull o2[16];
#pragma unroll
        for (int j = 0; j < 16; j++) o2[j] = __ldg(&b2b2[half * 16 + j]);
#pragma unroll 2
        for (int i2 = 0; i2 < 32; i2++) {
            float a, b;
            unpack2(h2[i2], a, b);
            accum_half(o2, sw2b + (2 * i2) * 64 + half * 32, pack2(a, a));
            accum_half(o2, sw2b + (2 * i2 + 1) * 64 + half * 32, pack2(b, b));
        }
#pragma unroll
        for (int j4 = 0; j4 < 8; j4++) {
            float f0, f1, f2, f3;
            unpack2(o2[2 * j4], f0, f1);
            unpack2(o2[2 * j4 + 1], f2, f3);
            ((float4*)(outp + half * 32))[j4] = make_float4(f0, f1, f2, f3);
        }
    }
}

extern "C" void kernel_launch(void* const* d_in, const int* in_sizes, int n_in,
                              void* d_out, int out_size) {
    const float* x   = (const float*)d_in[0];
    const int*   ei  = (const int*)d_in[1];
    const float* ea  = (const float*)d_in[2];
    // d_in[3] = u, d_in[4] = batch (unused by reference output)
    const float* w1a = (const float*)d_in[5];
    const float* b1a = (const float*)d_in[6];
    const float* w1b = (const float*)d_in[7];
    const float* b1b = (const float*)d_in[8];
    const float* w2a = (const float*)d_in[9];
    const float* b2a = (const float*)d_in[10];
    const float* w2b = (const float*)d_in[11];
    const float* b2b = (const float*)d_in[12];
    float* out = (float*)d_out;

    int N = in_sizes[0] / DD;
    int E = in_sizes[2] / DD;

    zero_summed<<<512, 256>>>(N * DD / 4);
    zero_counts<<<(N + 255) / 256, 256>>>(N);
    dim3 hxgrid((N + 127) / 128, 2);
    hx_kernel<<<hxgrid, 128>>>(x, w1a, b1a, w2a, b2a, N);
    edge_kernel<<<(E + 127) / 128, 128>>>(ei, ea, w1a, w1b, b1b, E);
    node_kernel<<<(N + 127) / 128, 128>>>(w2a, w2b, b2b, out, N);
}

// round 6
// speedup vs baseline: 3.6109x; 2.1141x over previous
#include <cuda_runtime.h>
#include <cuda_bf16.h>
#include <cstdint>

#define MAX_N 50016
#define DD 64

__device__ __align__(16) float g_summed[MAX_N * DD];
__device__ float g_counts[MAX_N];
__device__ __align__(16) float g_hx[MAX_N * DD];   // x @ w1a[0:64] + b1a
__device__ __align__(16) float g_hx2[MAX_N * DD];  // x @ w2a[0:64] + b2a

typedef unsigned long long ull;

// ---------- f32x2 packed-math helpers ----------
__device__ __forceinline__ ull ffma2(ull a, ull b, ull c) {
    ull d;
    asm("fma.rn.f32x2 %0, %1, %2, %3;" : "=l"(d) : "l"(a), "l"(b), "l"(c));
    return d;
}
__device__ __forceinline__ ull pack2(float lo, float hi) {
    ull r;
    asm("mov.b64 %0, {%1, %2};" : "=l"(r) : "f"(lo), "f"(hi));
    return r;
}
__device__ __forceinline__ void unpack2(ull v, float& lo, float& hi) {
    asm("mov.b64 {%0, %1}, %2;" : "=f"(lo), "=f"(hi) : "l"(v));
}
__device__ __forceinline__ ull relu2(ull v) {
    float a, b;
    unpack2(v, a, b);
    return pack2(fmaxf(a, 0.f), fmaxf(b, 0.f));
}
__device__ __forceinline__ void accum_row(ull* h2, const float* wrow, float s) {
    ull s2 = pack2(s, s);
    const ulonglong2* w = (const ulonglong2*)wrow;
#pragma unroll
    for (int j = 0; j < 16; j++) {
        ulonglong2 wv = w[j];
        h2[2 * j]     = ffma2(s2, wv.x, h2[2 * j]);
        h2[2 * j + 1] = ffma2(s2, wv.y, h2[2 * j + 1]);
    }
}
__device__ __forceinline__ void accum_half(ull* o2, const float* wrow, ull s2) {
    const ulonglong2* w = (const ulonglong2*)wrow;
#pragma unroll
    for (int j = 0; j < 8; j++) {
        ulonglong2 wv = w[j];
        o2[2 * j]     = ffma2(s2, wv.x, o2[2 * j]);
        o2[2 * j + 1] = ffma2(s2, wv.y, o2[2 * j + 1]);
    }
}

// ---------- tf32 + mma.sync helpers (sm_80 baseline, works on sm_103) ----------
__device__ __forceinline__ uint32_t f2tf32(float f) {
    uint32_t r;
    asm("cvt.rna.tf32.f32 %0, %1;" : "=r"(r) : "f"(f));
    return r;
}
// D(16x8) += A(16x8,tf32,row) * B(8x8,tf32,col); accumulate in-place
__device__ __forceinline__ void mma_tf32(float* d, const uint32_t* a,
                                         uint32_t b0, uint32_t b1) {
    asm volatile(
        "mma.sync.aligned.m16n8k8.row.col.f32.tf32.tf32.f32 "
        "{%0,%1,%2,%3}, {%4,%5,%6,%7}, {%8,%9}, {%0,%1,%2,%3};"
        : "+f"(d[0]), "+f"(d[1]), "+f"(d[2]), "+f"(d[3])
        : "r"(a[0]), "r"(a[1]), "r"(a[2]), "r"(a[3]), "r"(b0), "r"(b1));
}

// ---------- zero scratch ----------
__global__ void zero_summed(int n_f4) {
    int i = blockIdx.x * blockDim.x + threadIdx.x;
    int stride = gridDim.x * blockDim.x;
    float4 z = make_float4(0.f, 0.f, 0.f, 0.f);
    for (int j = i; j < n_f4; j += stride) ((float4*)g_summed)[j] = z;
}
__global__ void zero_counts(int n) {
    int i = blockIdx.x * blockDim.x + threadIdx.x;
    if (i < n) g_counts[i] = 0.f;
}

// ---------- per-node precompute ----------
__global__ void __launch_bounds__(128) hx_kernel(
    const float* __restrict__ x,
    const float* __restrict__ w1a, const float* __restrict__ b1a,
    const float* __restrict__ w2a, const float* __restrict__ b2a,
    int N) {
    __shared__ __align__(16) float sw[64 * 64];
    int which = blockIdx.y;
    const float* w = which ? w2a : w1a;
    const float* b = which ? b2a : b1a;
    for (int i = threadIdx.x; i < 64 * 64 / 4; i += blockDim.x)
        ((float4*)sw)[i] = ((const float4*)w)[i];
    __syncthreads();

    int n = blockIdx.x * blockDim.x + threadIdx.x;
    if (n >= N) return;

    ull h[32];
    const ull* b2 = (const ull*)b;
#pragma unroll
    for (int j = 0; j < 32; j++) h[j] = __ldg(&b2[j]);

    const float4* xin = (const float4*)(x + (size_t)n * DD);
#pragma unroll 2
    for (int k4 = 0; k4 < 16; k4++) {
        float4 v = __ldg(&xin[k4]);
        accum_row(h, sw + (4 * k4 + 0) * 64, v.x);
        accum_row(h, sw + (4 * k4 + 1) * 64, v.y);
        accum_row(h, sw + (4 * k4 + 2) * 64, v.z);
        accum_row(h, sw + (4 * k4 + 3) * 64, v.w);
    }
    float* dst = (which ? g_hx2 : g_hx) + (size_t)n * DD;
#pragma unroll
    for (int j = 0; j < 32; j++) ((ull*)dst)[j] = h[j];
}

// ---------- edge kernel: tensor-core (mma.sync tf32) double GEMM + scatter ----------
// CTA = 256 thr (8 warps), persistent; each warp handles 32 edges per tile.
// smem: sw1[64k x 72] (w1a bottom, [k][n]) | sw2[64 x 72] (w1b, [k][n])
//       | sb1b[64] | per-warp A/H tile [32 x 68]
#define SW1_OFF 0
#define SW2_OFF 18432
#define SB1B_OFF 36864
#define SEA_OFF 37120
#define SEA_WARP_BYTES 8704  // 32*68*4
#define SMEM_EDGE (SEA_OFF + 8 * SEA_WARP_BYTES)  // 106752

__global__ void __launch_bounds__(256, 2) edge_mma_kernel(
    const int* __restrict__ ei, const float* __restrict__ ea,
    const float* __restrict__ w1a,  // rows 64..127 used
    const float* __restrict__ w1b, const float* __restrict__ b1b,
    int E, int ntiles) {
    extern __shared__ __align__(16) char dsm[];
    uint32_t* sw1 = (uint32_t*)(dsm + SW1_OFF);
    uint32_t* sw2 = (uint32_t*)(dsm + SW2_OFF);
    float* sb1b = (float*)(dsm + SB1B_OFF);

    int tid = threadIdx.x;
    int wid = tid >> 5, l = tid & 31;
    int gid = l >> 2, tig = l & 3;
    uint32_t* se = (uint32_t*)(dsm + SEA_OFF) + wid * 2176;  // 32 rows x 68 stride

    // stage weights as tf32 [k][n], stride 72 (bank-conflict-free B frags)
    for (int idx = tid; idx < 4096; idx += 256) {
        int k = idx >> 6, n = idx & 63;
        sw1[k * 72 + n] = f2tf32(w1a[(64 + k) * 64 + n]);
        sw2[k * 72 + n] = f2tf32(w1b[k * 64 + n]);
    }
    if (tid < 64) sb1b[tid] = b1b[tid];
    __syncthreads();

    for (int tile = blockIdx.x; tile < ntiles; tile += gridDim.x) {
        long long eb = (long long)tile * 256 + wid * 32;  // warp's edge base
        long long ee = eb + l;
        bool ev = (ee < E);
        int rsrc = ev ? ei[ee] : 0;
        int cdst = ev ? ei[E + ee] : 0;

        __syncwarp();
        // stage ea tile (32 edges x 64) as tf32 into per-warp smem
#pragma unroll
        for (int i = 0; i < 16; i++) {
            int idx = l + 32 * i;
            int row = idx >> 4, k4 = (idx & 15) * 4;
            long long er = eb + row;
            float4 v = (er < E) ? __ldg((const float4*)(ea + er * 64 + k4))
                                : make_float4(0.f, 0.f, 0.f, 0.f);
            uint4 s;
            s.x = f2tf32(v.x); s.y = f2tf32(v.y); s.z = f2tf32(v.z); s.w = f2tf32(v.w);
            *(uint4*)(se + row * 68 + k4) = s;
        }
        __syncwarp();

        float c[2][8][4];
#pragma unroll
        for (int mt = 0; mt < 2; mt++)
#pragma unroll
            for (int j = 0; j < 8; j++)
#pragma unroll
                for (int r = 0; r < 4; r++) c[mt][j][r] = 0.f;

        // ---- layer 1: C = EA @ W1^T ----
#pragma unroll
        for (int kt = 0; kt < 8; kt++) {
            uint32_t a[2][4];
#pragma unroll
            for (int mt = 0; mt < 2; mt++) {
                int r0 = mt * 16 + gid;
                a[mt][0] = se[r0 * 68 + kt * 8 + tig];
                a[mt][1] = se[(r0 + 8) * 68 + kt * 8 + tig];
                a[mt][2] = se[r0 * 68 + kt * 8 + tig + 4];
                a[mt][3] = se[(r0 + 8) * 68 + kt * 8 + tig + 4];
            }
#pragma unroll
            for (int j = 0; j < 8; j++) {
                uint32_t b0 = sw1[(kt * 8 + tig) * 72 + j * 8 + gid];
                uint32_t b1 = sw1[(kt * 8 + tig + 4) * 72 + j * 8 + gid];
                mma_tf32(c[0][j], a[0], b0, b1);
                mma_tf32(c[1][j], a[1], b0, b1);
            }
        }
        __syncwarp();

        // ---- epilogue 1: h = relu(C + hx[src]) -> tf32 back into smem tile ----
#pragma unroll
        for (int mt = 0; mt < 2; mt++) {
            int rlo = __shfl_sync(0xffffffffu, rsrc, mt * 16 + gid);
            int rhi = __shfl_sync(0xffffffffu, rsrc, mt * 16 + gid + 8);
            const float* hlo = g_hx + (size_t)rlo * DD + 2 * tig;
            const float* hhi = g_hx + (size_t)rhi * DD + 2 * tig;
            int r0 = mt * 16 + gid;
#pragma unroll
            for (int j = 0; j < 8; j++) {
                float2 xl = __ldg((const float2*)(hlo + j * 8));
                float2 xh = __ldg((const float2*)(hhi + j * 8));
                uint2 lo, hi;
                lo.x = f2tf32(fmaxf(c[mt][j][0] + xl.x, 0.f));
                lo.y = f2tf32(fmaxf(c[mt][j][1] + xl.y, 0.f));
                hi.x = f2tf32(fmaxf(c[mt][j][2] + xh.x, 0.f));
                hi.y = f2tf32(fmaxf(c[mt][j][3] + xh.y, 0.f));
                *(uint2*)(se + r0 * 68 + j * 8 + 2 * tig) = lo;
                *(uint2*)(se + (r0 + 8) * 68 + j * 8 + 2 * tig) = hi;
                c[mt][j][0] = 0.f; c[mt][j][1] = 0.f;
                c[mt][j][2] = 0.f; c[mt][j][3] = 0.f;
            }
        }
        __syncwarp();

        // ---- layer 2: C = H @ W2^T ----
#pragma unroll
        for (int kt = 0; kt < 8; kt++) {
            uint32_t a[2][4];
#pragma unroll
            for (int mt = 0; mt < 2; mt++) {
                int r0 = mt * 16 + gid;
                a[mt][0] = se[r0 * 68 + kt * 8 + tig];
                a[mt][1] = se[(r0 + 8) * 68 + kt * 8 + tig];
                a[mt][2] = se[r0 * 68 + kt * 8 + tig + 4];
                a[mt][3] = se[(r0 + 8) * 68 + kt * 8 + tig + 4];
            }
#pragma unroll
            for (int j = 0; j < 8; j++) {
                uint32_t b0 = sw2[(kt * 8 + tig) * 72 + j * 8 + gid];
                uint32_t b1 = sw2[(kt * 8 + tig + 4) * 72 + j * 8 + gid];
                mma_tf32(c[0][j], a[0], b0, b1);
                mma_tf32(c[1][j], a[1], b0, b1);
            }
        }

        // ---- epilogue 2: scatter-add (C + b1b) into g_summed[dst] ----
#pragma unroll
        for (int mt = 0; mt < 2; mt++) {
            int clo = __shfl_sync(0xffffffffu, cdst, mt * 16 + gid);
            int chi = __shfl_sync(0xffffffffu, cdst, mt * 16 + gid + 8);
            bool vlo = (eb + mt * 16 + gid) < E;
            bool vhi = (eb + mt * 16 + gid + 8) < E;
            float* dlo = g_summed + (size_t)clo * DD + 2 * tig;
            float* dhi = g_summed + (size_t)chi * DD + 2 * tig;
#pragma unroll
            for (int j = 0; j < 8; j++) {
                float2 bb = *(const float2*)(sb1b + j * 8 + 2 * tig);
                if (vlo) {
                    float f0 = c[mt][j][0] + bb.x;
                    float f1 = c[mt][j][1] + bb.y;
                    asm volatile("red.global.add.v2.f32 [%0], {%1,%2};"
                                 :: "l"(dlo + j * 8), "f"(f0), "f"(f1) : "memory");
                }
                if (vhi) {
                    float f2 = c[mt][j][2] + bb.x;
                    float f3 = c[mt][j][3] + bb.y;
                    asm volatile("red.global.add.v2.f32 [%0], {%1,%2};"
                                 :: "l"(dhi + j * 8), "f"(f2), "f"(f3) : "memory");
                }
            }
        }
        if (ev) atomicAdd(&g_counts[cdst], 1.0f);
    }
}

// ---------- fused node MLP (uses precomputed hx2) ----------
__global__ void __launch_bounds__(128) node_kernel(
    const float* __restrict__ w2a,
    const float* __restrict__ w2b, const float* __restrict__ b2b,
    float* __restrict__ out, int N) {
    __shared__ __align__(16) float sw2a[64 * 64];
    __shared__ __align__(16) float sw2b[64 * 64];

    for (int i = threadIdx.x; i < 64 * 64 / 4; i += blockDim.x) {
        ((float4*)sw2a)[i] = ((const float4*)(w2a + 64 * 64))[i];
        ((float4*)sw2b)[i] = ((const float4*)w2b)[i];
    }
    __syncthreads();

    int n = blockIdx.x * blockDim.x + threadIdx.x;
    if (n >= N) return;

    ull h2[32];
    const ull* hxp = (const ull*)(g_hx2 + (size_t)n * DD);
#pragma unroll
    for (int j = 0; j < 32; j++) h2[j] = __ldg(&hxp[j]);

    float cnt = g_counts[n];
    float inv = 1.0f / fmaxf(cnt, 1.0f);
    const float4* ag = (const float4*)(g_summed + (size_t)n * DD);
#pragma unroll 2
    for (int k4 = 0; k4 < 16; k4++) {
        float4 v = ag[k4];
        accum_row(h2, sw2a + (4 * k4 + 0) * 64, v.x * inv);
        accum_row(h2, sw2a + (4 * k4 + 1) * 64, v.y * inv);
        accum_row(h2, sw2a + (4 * k4 + 2) * 64, v.z * inv);
        accum_row(h2, sw2a + (4 * k4 + 3) * 64, v.w * inv);
    }

#pragma unroll
    for (int j = 0; j < 32; j++) h2[j] = relu2(h2[j]);

    float* outp = out + (size_t)n * DD;
    const ull* b2b2 = (const ull*)b2b;
#pragma unroll 1
    for (int half = 0; half < 2; half++) {
        ull o2[16];
#pragma unroll
        for (int j = 0; j < 16; j++) o2[j] = __ldg(&b2b2[half * 16 + j]);
#pragma unroll 2
        for (int i2 = 0; i2 < 32; i2++) {
            float a, b;
            unpack2(h2[i2], a, b);
            accum_half(o2, sw2b + (2 * i2) * 64 + half * 32, pack2(a, a));
            accum_half(o2, sw2b + (2 * i2 + 1) * 64 + half * 32, pack2(b, b));
        }
#pragma unroll
        for (int j4 = 0; j4 < 8; j4++) {
            float f0, f1, f2, f3;
            unpack2(o2[2 * j4], f0, f1);
            unpack2(o2[2 * j4 + 1], f2, f3);
            ((float4*)(outp + half * 32))[j4] = make_float4(f0, f1, f2, f3);
        }
    }
}

extern "C" void kernel_launch(void* const* d_in, const int* in_sizes, int n_in,
                              void* d_out, int out_size) {
    const float* x   = (const float*)d_in[0];
    const int*   ei  = (const int*)d_in[1];
    const float* ea  = (const float*)d_in[2];
    const float* w1a = (const float*)d_in[5];
    const float* b1a = (const float*)d_in[6];
    const float* w1b = (const float*)d_in[7];
    const float* b1b = (const float*)d_in[8];
    const float* w2a = (const float*)d_in[9];
    const float* b2a = (const float*)d_in[10];
    const float* w2b = (const float*)d_in[11];
    const float* b2b = (const float*)d_in[12];
    float* out = (float*)d_out;

    int N = in_sizes[0] / DD;
    int E = in_sizes[2] / DD;

    cudaFuncSetAttribute(edge_mma_kernel,
                         cudaFuncAttributeMaxDynamicSharedMemorySize, SMEM_EDGE);

    int ntiles = (E + 255) / 256;
    int grid = ntiles < 296 ? ntiles : 296;

    zero_summed<<<512, 256>>>(N * DD / 4);
    zero_counts<<<(N + 255) / 256, 256>>>(N);
    dim3 hxgrid((N + 127) / 128, 2);
    hx_kernel<<<hxgrid, 128>>>(x, w1a, b1a, w2a, b2a, N);
    edge_mma_kernel<<<grid, 256, SMEM_EDGE>>>(ei, ea, w1a, w1b, b1b, E, ntiles);
    node_kernel<<<(N + 127) / 128, 128>>>(w2a, w2b, b2b, out, N);
}

// round 8
// speedup vs baseline: 4.4756x; 1.2395x over previous
#include <cuda_runtime.h>
#include <cuda_bf16.h>
#include <cstdint>

#define MAX_N 50016
#define DD 64

__device__ __align__(16) float g_summed[MAX_N * DD];
__device__ float g_counts[MAX_N];
__device__ __align__(16) float g_hx[MAX_N * DD];   // x @ w1a[0:64] + b1a
__device__ __align__(16) float g_hx2[MAX_N * DD];  // x @ w2a[0:64] + b2a

// ---------- tf32 + mma helpers ----------
__device__ __forceinline__ uint32_t f2tf32(float f) {
    uint32_t r;
    asm("cvt.rna.tf32.f32 %0, %1;" : "=r"(r) : "f"(f));
    return r;
}
// D(16x8,f32) += A(16x8,tf32,row) * B(8x8,tf32,col)
__device__ __forceinline__ void mma_tf32(float* d, const uint32_t* a,
                                         uint32_t b0, uint32_t b1) {
    asm volatile(
        "mma.sync.aligned.m16n8k8.row.col.f32.tf32.tf32.f32 "
        "{%0,%1,%2,%3}, {%4,%5,%6,%7}, {%8,%9}, {%0,%1,%2,%3};"
        : "+f"(d[0]), "+f"(d[1]), "+f"(d[2]), "+f"(d[3])
        : "r"(a[0]), "r"(a[1]), "r"(a[2]), "r"(a[3]), "r"(b0), "r"(b1));
}

// Warp GEMM: C[32x64] += A(se: 32 rows x 64 k, stride 68) * B(sw: [k][n] stride 72)^T
__device__ __forceinline__ void warp_gemm(const uint32_t* se, const uint32_t* sw,
                                          int gid, int tig, float c[2][8][4]) {
#pragma unroll
    for (int kt = 0; kt < 8; kt++) {
        uint32_t a[2][4];
#pragma unroll
        for (int mt = 0; mt < 2; mt++) {
            int r0 = mt * 16 + gid;
            a[mt][0] = se[r0 * 68 + kt * 8 + tig];
            a[mt][1] = se[(r0 + 8) * 68 + kt * 8 + tig];
            a[mt][2] = se[r0 * 68 + kt * 8 + tig + 4];
            a[mt][3] = se[(r0 + 8) * 68 + kt * 8 + tig + 4];
        }
#pragma unroll
        for (int j = 0; j < 8; j++) {
            uint32_t b0 = sw[(kt * 8 + tig) * 72 + j * 8 + gid];
            uint32_t b1 = sw[(kt * 8 + tig + 4) * 72 + j * 8 + gid];
            mma_tf32(c[0][j], a[0], b0, b1);
            mma_tf32(c[1][j], a[1], b0, b1);
        }
    }
}

__device__ __forceinline__ void zero_c(float c[2][8][4]) {
#pragma unroll
    for (int mt = 0; mt < 2; mt++)
#pragma unroll
        for (int j = 0; j < 8; j++)
#pragma unroll
            for (int r = 0; r < 4; r++) c[mt][j][r] = 0.f;
}

// ---------- zero scratch ----------
__global__ void zero_summed(int n_f4) {
    int i = blockIdx.x * blockDim.x + threadIdx.x;
    int stride = gridDim.x * blockDim.x;
    float4 z = make_float4(0.f, 0.f, 0.f, 0.f);
    for (int j = i; j < n_f4; j += stride) ((float4*)g_summed)[j] = z;
}
__global__ void zero_counts(int n) {
    int i = blockIdx.x * blockDim.x + threadIdx.x;
    if (i < n) g_counts[i] = 0.f;
}

// Shared smem layout constants (all mma kernels)
// SW1 [64k x 72] u32 | SW2 [64k x 72] u32 | SB[64] f32 | SB2[64] f32 | 8 x warp tile 32x68 u32
#define SM_SW1 0
#define SM_SW2 18432
#define SM_SB 36864
#define SM_SB2 37120
#define SM_SE 37376
#define SM_TOTAL (SM_SE + 8 * 32 * 68 * 4)  // 107008

// ================= hx kernel: hx = x@w1a_top + b1a, hx2 = x@w2a_top + b2a =================
__global__ void __launch_bounds__(256, 2) hx_mma_kernel(
    const float* __restrict__ x,
    const float* __restrict__ w1a, const float* __restrict__ b1a,
    const float* __restrict__ w2a, const float* __restrict__ b2a,
    int N) {
    extern __shared__ __align__(16) char dsm[];
    uint32_t* sw1 = (uint32_t*)(dsm + SM_SW1);
    uint32_t* sw2 = (uint32_t*)(dsm + SM_SW2);
    float* sb1 = (float*)(dsm + SM_SB);
    float* sb2 = (float*)(dsm + SM_SB2);

    int tid = threadIdx.x;
    int wid = tid >> 5, l = tid & 31;
    int gid = l >> 2, tig = l & 3;
    uint32_t* se = (uint32_t*)(dsm + SM_SE) + wid * 2176;

    for (int idx = tid; idx < 4096; idx += 256) {
        int k = idx >> 6, n = idx & 63;
        sw1[k * 72 + n] = f2tf32(w1a[k * 64 + n]);  // top rows 0..63
        sw2[k * 72 + n] = f2tf32(w2a[k * 64 + n]);
    }
    if (tid < 64) sb1[tid] = b1a[tid];
    else if (tid < 128) sb2[tid - 64] = b2a[tid - 64];
    __syncthreads();

    long long base = (long long)blockIdx.x * 256 + wid * 32;

    // stage x tile (32 rows x 64) tf32
#pragma unroll
    for (int i = 0; i < 16; i++) {
        int idx = l + 32 * i;
        int row = idx >> 4, k4 = (idx & 15) * 4;
        long long r = base + row;
        float4 v = (r < N) ? __ldg((const float4*)(x + r * 64 + k4))
                           : make_float4(0.f, 0.f, 0.f, 0.f);
        uint4 s;
        s.x = f2tf32(v.x); s.y = f2tf32(v.y); s.z = f2tf32(v.z); s.w = f2tf32(v.w);
        *(uint4*)(se + row * 68 + k4) = s;
    }
    __syncwarp();

    float c[2][8][4];
#pragma unroll 1
    for (int p = 0; p < 2; p++) {
        zero_c(c);
        warp_gemm(se, p ? sw2 : sw1, gid, tig, c);
        float* outg = p ? g_hx2 : g_hx;
        const float* sb = p ? sb2 : sb1;
#pragma unroll
        for (int mt = 0; mt < 2; mt++) {
            long long r0 = base + mt * 16 + gid;
#pragma unroll
            for (int j = 0; j < 8; j++) {
                float2 bb = *(const float2*)(sb + j * 8 + 2 * tig);
                if (r0 < N)
                    *(float2*)(outg + r0 * 64 + j * 8 + 2 * tig) =
                        make_float2(c[mt][j][0] + bb.x, c[mt][j][1] + bb.y);
                if (r0 + 8 < N)
                    *(float2*)(outg + (r0 + 8) * 64 + j * 8 + 2 * tig) =
                        make_float2(c[mt][j][2] + bb.x, c[mt][j][3] + bb.y);
            }
        }
    }
}

// ================= edge kernel: tf32 tensor-core double GEMM + scatter =================
__global__ void __launch_bounds__(256, 2) edge_mma_kernel(
    const int* __restrict__ ei, const float* __restrict__ ea,
    const float* __restrict__ w1a,  // rows 64..127 used
    const float* __restrict__ w1b, const float* __restrict__ b1b,
    int E, int ntiles) {
    extern __shared__ __align__(16) char dsm[];
    uint32_t* sw1 = (uint32_t*)(dsm + SM_SW1);
    uint32_t* sw2 = (uint32_t*)(dsm + SM_SW2);
    float* sb1b = (float*)(dsm + SM_SB);

    int tid = threadIdx.x;
    int wid = tid >> 5, l = tid & 31;
    int gid = l >> 2, tig = l & 3;
    uint32_t* se = (uint32_t*)(dsm + SM_SE) + wid * 2176;

    for (int idx = tid; idx < 4096; idx += 256) {
        int k = idx >> 6, n = idx & 63;
        sw1[k * 72 + n] = f2tf32(w1a[(64 + k) * 64 + n]);
        sw2[k * 72 + n] = f2tf32(w1b[k * 64 + n]);
    }
    if (tid < 64) sb1b[tid] = b1b[tid];
    __syncthreads();

    for (int tile = blockIdx.x; tile < ntiles; tile += gridDim.x) {
        long long eb = (long long)tile * 256 + wid * 32;
        long long ee = eb + l;
        bool ev = (ee < E);
        int rsrc = ev ? ei[ee] : 0;
        int cdst = ev ? ei[E + ee] : 0;

        __syncwarp();
        // stage ea tile (32 edges x 64) tf32
#pragma unroll
        for (int i = 0; i < 16; i++) {
            int idx = l + 32 * i;
            int row = idx >> 4, k4 = (idx & 15) * 4;
            long long er = eb + row;
            float4 v = (er < E) ? __ldg((const float4*)(ea + er * 64 + k4))
                                : make_float4(0.f, 0.f, 0.f, 0.f);
            uint4 s;
            s.x = f2tf32(v.x); s.y = f2tf32(v.y); s.z = f2tf32(v.z); s.w = f2tf32(v.w);
            *(uint4*)(se + row * 68 + k4) = s;
        }
        __syncwarp();

        float c[2][8][4];
        zero_c(c);

        // ---- layer 1: C = EA @ W1_bot^T ----
        warp_gemm(se, sw1, gid, tig, c);
        __syncwarp();

        // ---- epilogue 1: h = relu(C + hx[src]) -> tf32 back into smem tile ----
#pragma unroll
        for (int mt = 0; mt < 2; mt++) {
            int rlo = __shfl_sync(0xffffffffu, rsrc, mt * 16 + gid);
            int rhi = __shfl_sync(0xffffffffu, rsrc, mt * 16 + gid + 8);
            const float* hlo = g_hx + (size_t)rlo * DD + 2 * tig;
            const float* hhi = g_hx + (size_t)rhi * DD + 2 * tig;
            int r0 = mt * 16 + gid;
#pragma unroll
            for (int j = 0; j < 8; j++) {
                float2 xl = __ldg((const float2*)(hlo + j * 8));
                float2 xh = __ldg((const float2*)(hhi + j * 8));
                uint2 lo, hi;
                lo.x = f2tf32(fmaxf(c[mt][j][0] + xl.x, 0.f));
                lo.y = f2tf32(fmaxf(c[mt][j][1] + xl.y, 0.f));
                hi.x = f2tf32(fmaxf(c[mt][j][2] + xh.x, 0.f));
                hi.y = f2tf32(fmaxf(c[mt][j][3] + xh.y, 0.f));
                *(uint2*)(se + r0 * 68 + j * 8 + 2 * tig) = lo;
                *(uint2*)(se + (r0 + 8) * 68 + j * 8 + 2 * tig) = hi;
                c[mt][j][0] = 0.f; c[mt][j][1] = 0.f;
                c[mt][j][2] = 0.f; c[mt][j][3] = 0.f;
            }
        }
        __syncwarp();

        // ---- layer 2: C = H @ W2^T ----
        warp_gemm(se, sw2, gid, tig, c);

        // ---- epilogue 2: scatter-add (C + b1b) ----
#pragma unroll
        for (int mt = 0; mt < 2; mt++) {
            int clo = __shfl_sync(0xffffffffu, cdst, mt * 16 + gid);
            int chi = __shfl_sync(0xffffffffu, cdst, mt * 16 + gid + 8);
            bool vlo = (eb + mt * 16 + gid) < E;
            bool vhi = (eb + mt * 16 + gid + 8) < E;
            float* dlo = g_summed + (size_t)clo * DD + 2 * tig;
            float* dhi = g_summed + (size_t)chi * DD + 2 * tig;
#pragma unroll
            for (int j = 0; j < 8; j++) {
                float2 bb = *(const float2*)(sb1b + j * 8 + 2 * tig);
                if (vlo) {
                    float f0 = c[mt][j][0] + bb.x;
                    float f1 = c[mt][j][1] + bb.y;
                    asm volatile("red.global.add.v2.f32 [%0], {%1,%2};"
                                 :: "l"(dlo + j * 8), "f"(f0), "f"(f1) : "memory");
                }
                if (vhi) {
                    float f2 = c[mt][j][2] + bb.x;
                    float f3 = c[mt][j][3] + bb.y;
                    asm volatile("red.global.add.v2.f32 [%0], {%1,%2};"
                                 :: "l"(dhi + j * 8), "f"(f2), "f"(f3) : "memory");
                }
            }
        }
        if (ev) atomicAdd(&g_counts[cdst], 1.0f);
    }
}

// ================= node kernel: out = relu(agg@w2a_bot + hx2) @ w2b + b2b =================
__global__ void __launch_bounds__(256, 2) node_mma_kernel(
    const float* __restrict__ w2a,  // rows 64..127 used
    const float* __restrict__ w2b, const float* __restrict__ b2b,
    float* __restrict__ out, int N) {
    extern __shared__ __align__(16) char dsm[];
    uint32_t* sw1 = (uint32_t*)(dsm + SM_SW1);
    uint32_t* sw2 = (uint32_t*)(dsm + SM_SW2);
    float* sbb = (float*)(dsm + SM_SB);

    int tid = threadIdx.x;
    int wid = tid >> 5, l = tid & 31;
    int gid = l >> 2, tig = l & 3;
    uint32_t* se = (uint32_t*)(dsm + SM_SE) + wid * 2176;

    for (int idx = tid; idx < 4096; idx += 256) {
        int k = idx >> 6, n = idx & 63;
        sw1[k * 72 + n] = f2tf32(w2a[(64 + k) * 64 + n]);
        sw2[k * 72 + n] = f2tf32(w2b[k * 64 + n]);
    }
    if (tid < 64) sbb[tid] = b2b[tid];
    __syncthreads();

    long long base = (long long)blockIdx.x * 256 + wid * 32;

    // stage agg tile = g_summed[row]/max(count,1) as tf32
#pragma unroll
    for (int i = 0; i < 16; i++) {
        int idx = l + 32 * i;
        int row = idx >> 4, k4 = (idx & 15) * 4;
        long long r = base + row;
        float4 v = make_float4(0.f, 0.f, 0.f, 0.f);
        if (r < N) {
            float inv = 1.0f / fmaxf(g_counts[r], 1.0f);
            float4 s = *(const float4*)(g_summed + r * 64 + k4);
            v = make_float4(s.x * inv, s.y * inv, s.z * inv, s.w * inv);
        }
        uint4 s;
        s.x = f2tf32(v.x); s.y = f2tf32(v.y); s.z = f2tf32(v.z); s.w = f2tf32(v.w);
        *(uint4*)(se + row * 68 + k4) = s;
    }
    __syncwarp();

    float c[2][8][4];
    zero_c(c);
    warp_gemm(se, sw1, gid, tig, c);
    __syncwarp();

    // epilogue 1: h = relu(C + hx2[row]) -> tf32
#pragma unroll
    for (int mt = 0; mt < 2; mt++) {
        long long r0 = base + mt * 16 + gid;
        long long rlo = (r0 < N) ? r0 : 0;
        long long rhi = (r0 + 8 < N) ? r0 + 8 : 0;
        const float* hlo = g_hx2 + rlo * DD + 2 * tig;
        const float* hhi = g_hx2 + rhi * DD + 2 * tig;
        int rr = mt * 16 + gid;
#pragma unroll
        for (int j = 0; j < 8; j++) {
            float2 xl = __ldg((const float2*)(hlo + j * 8));
            float2 xh = __ldg((const float2*)(hhi + j * 8));
            uint2 lo, hi;
            lo.x = f2tf32(fmaxf(c[mt][j][0] + xl.x, 0.f));
            lo.y = f2tf32(fmaxf(c[mt][j][1] + xl.y, 0.f));
            hi.x = f2tf32(fmaxf(c[mt][j][2] + xh.x, 0.f));
            hi.y = f2tf32(fmaxf(c[mt][j][3] + xh.y, 0.f));
            *(uint2*)(se + rr * 68 + j * 8 + 2 * tig) = lo;
            *(uint2*)(se + (rr + 8) * 68 + j * 8 + 2 * tig) = hi;
            c[mt][j][0] = 0.f; c[mt][j][1] = 0.f;
            c[mt][j][2] = 0.f; c[mt][j][3] = 0.f;
        }
    }
    __syncwarp();

    warp_gemm(se, sw2, gid, tig, c);

    // epilogue 2: out = C + b2b
#pragma unroll
    for (int mt = 0; mt < 2; mt++) {
        long long r0 = base + mt * 16 + gid;
#pragma unroll
        for (int j = 0; j < 8; j++) {
            float2 bb = *(const float2*)(sbb + j * 8 + 2 * tig);
            if (r0 < N)
                *(float2*)(out + r0 * 64 + j * 8 + 2 * tig) =
                    make_float2(c[mt][j][0] + bb.x, c[mt][j][1] + bb.y);
            if (r0 + 8 < N)
                *(float2*)(out + (r0 + 8) * 64 + j * 8 + 2 * tig) =
                    make_float2(c[mt][j][2] + bb.x, c[mt][j][3] + bb.y);
        }
    }
}

extern "C" void kernel_launch(void* const* d_in, const int* in_sizes, int n_in,
                              void* d_out, int out_size) {
    const float* x   = (const float*)d_in[0];
    const int*   ei  = (const int*)d_in[1];
    const float* ea  = (const float*)d_in[2];
    const float* w1a = (const float*)d_in[5];
    const float* b1a = (const float*)d_in[6];
    const float* w1b = (const float*)d_in[7];
    const float* b1b = (const float*)d_in[8];
    const float* w2a = (const float*)d_in[9];
    const float* b2a = (const float*)d_in[10];
    const float* w2b = (const float*)d_in[11];
    const float* b2b = (const float*)d_in[12];
    float* out = (float*)d_out;

    int N = in_sizes[0] / DD;
    int E = in_sizes[2] / DD;

    cudaFuncSetAttribute(hx_mma_kernel, cudaFuncAttributeMaxDynamicSharedMemorySize, SM_TOTAL);
    cudaFuncSetAttribute(edge_mma_kernel, cudaFuncAttributeMaxDynamicSharedMemorySize, SM_TOTAL);
    cudaFuncSetAttribute(node_mma_kernel, cudaFuncAttributeMaxDynamicSharedMemorySize, SM_TOTAL);

    int ntiles_e = (E + 255) / 256;
    int grid_e = ntiles_e < 296 ? ntiles_e : 296;
    int ntiles_n = (N + 255) / 256;

    zero_summed<<<512, 256>>>(N * DD / 4);
    zero_counts<<<(N + 255) / 256, 256>>>(N);
    hx_mma_kernel<<<ntiles_n, 256, SM_TOTAL>>>(x, w1a, b1a, w2a, b2a, N);
    edge_mma_kernel<<<grid_e, 256, SM_TOTAL>>>(ei, ea, w1a, w1b, b1b, E, ntiles_e);
    node_mma_kernel<<<ntiles_n, 256, SM_TOTAL>>>(w2a, w2b, b2b, out, N);
}

// round 9
// speedup vs baseline: 4.7644x; 1.0645x over previous
#include <cuda_runtime.h>
#include <cuda_bf16.h>
#include <cstdint>

#define MAX_N 50432
#define DD 64

__device__ __align__(16) float g_summed[MAX_N * DD];  // sum of relu(h_e) per dst node
__device__ float g_counts[MAX_N];
__device__ __align__(16) float g_hx[MAX_N * DD];   // x @ w1a[0:64] + b1a
__device__ __align__(16) float g_hx2[MAX_N * DD];  // x @ w2a[0:64] + b2a

// ---------- tf32 + mma helpers ----------
__device__ __forceinline__ uint32_t f2tf32(float f) {
    uint32_t r;
    asm("cvt.rna.tf32.f32 %0, %1;" : "=r"(r) : "f"(f));
    return r;
}
// D(16x8,f32) += A(16x8,tf32,row) * B(8x8,tf32,col)
__device__ __forceinline__ void mma_tf32(float* d, const uint32_t* a,
                                         uint32_t b0, uint32_t b1) {
    asm volatile(
        "mma.sync.aligned.m16n8k8.row.col.f32.tf32.tf32.f32 "
        "{%0,%1,%2,%3}, {%4,%5,%6,%7}, {%8,%9}, {%0,%1,%2,%3};"
        : "+f"(d[0]), "+f"(d[1]), "+f"(d[2]), "+f"(d[3])
        : "r"(a[0]), "r"(a[1]), "r"(a[2]), "r"(a[3]), "r"(b0), "r"(b1));
}

// Warp GEMM: C[32x64] += A(se: 32 rows x 64 k, stride 68) * B(sw: [k][n] stride 72)^T
__device__ __forceinline__ void warp_gemm(const uint32_t* se, const uint32_t* sw,
                                          int gid, int tig, float c[2][8][4]) {
#pragma unroll
    for (int kt = 0; kt < 8; kt++) {
        uint32_t a[2][4];
#pragma unroll
        for (int mt = 0; mt < 2; mt++) {
            int r0 = mt * 16 + gid;
            a[mt][0] = se[r0 * 68 + kt * 8 + tig];
            a[mt][1] = se[(r0 + 8) * 68 + kt * 8 + tig];
            a[mt][2] = se[r0 * 68 + kt * 8 + tig + 4];
            a[mt][3] = se[(r0 + 8) * 68 + kt * 8 + tig + 4];
        }
#pragma unroll
        for (int j = 0; j < 8; j++) {
            uint32_t b0 = sw[(kt * 8 + tig) * 72 + j * 8 + gid];
            uint32_t b1 = sw[(kt * 8 + tig + 4) * 72 + j * 8 + gid];
            mma_tf32(c[0][j], a[0], b0, b1);
            mma_tf32(c[1][j], a[1], b0, b1);
        }
    }
}

__device__ __forceinline__ void zero_c(float c[2][8][4]) {
#pragma unroll
    for (int mt = 0; mt < 2; mt++)
#pragma unroll
        for (int j = 0; j < 8; j++)
#pragma unroll
            for (int r = 0; r < 4; r++) c[mt][j][r] = 0.f;
}

// ---------- zero scratch ----------
__global__ void zero_summed(int n_f4) {
    int i = blockIdx.x * blockDim.x + threadIdx.x;
    int stride = gridDim.x * blockDim.x;
    float4 z = make_float4(0.f, 0.f, 0.f, 0.f);
    for (int j = i; j < n_f4; j += stride) ((float4*)g_summed)[j] = z;
}
__global__ void zero_counts(int n) {
    int i = blockIdx.x * blockDim.x + threadIdx.x;
    if (i < n) g_counts[i] = 0.f;
}

// ================= hx kernel: hx = x@w1a_top + b1a, hx2 = x@w2a_top + b2a =================
#define HX_SW1 0
#define HX_SW2 18432
#define HX_SB 36864
#define HX_SB2 37120
#define HX_SE 37376
#define HX_SMEM (HX_SE + 8 * 32 * 68 * 4)  // 107008

__global__ void __launch_bounds__(256, 2) hx_mma_kernel(
    const float* __restrict__ x,
    const float* __restrict__ w1a, const float* __restrict__ b1a,
    const float* __restrict__ w2a, const float* __restrict__ b2a,
    int N) {
    extern __shared__ __align__(16) char dsm[];
    uint32_t* sw1 = (uint32_t*)(dsm + HX_SW1);
    uint32_t* sw2 = (uint32_t*)(dsm + HX_SW2);
    float* sb1 = (float*)(dsm + HX_SB);
    float* sb2 = (float*)(dsm + HX_SB2);

    int tid = threadIdx.x;
    int wid = tid >> 5, l = tid & 31;
    int gid = l >> 2, tig = l & 3;
    uint32_t* se = (uint32_t*)(dsm + HX_SE) + wid * 2176;

    for (int idx = tid; idx < 4096; idx += 256) {
        int k = idx >> 6, n = idx & 63;
        sw1[k * 72 + n] = f2tf32(w1a[k * 64 + n]);  // top rows 0..63
        sw2[k * 72 + n] = f2tf32(w2a[k * 64 + n]);
    }
    if (tid < 64) sb1[tid] = b1a[tid];
    else if (tid < 128) sb2[tid - 64] = b2a[tid - 64];
    __syncthreads();

    long long base = (long long)blockIdx.x * 256 + wid * 32;

#pragma unroll
    for (int i = 0; i < 16; i++) {
        int idx = l + 32 * i;
        int row = idx >> 4, k4 = (idx & 15) * 4;
        long long r = base + row;
        float4 v = (r < N) ? __ldg((const float4*)(x + r * 64 + k4))
                           : make_float4(0.f, 0.f, 0.f, 0.f);
        uint4 s;
        s.x = f2tf32(v.x); s.y = f2tf32(v.y); s.z = f2tf32(v.z); s.w = f2tf32(v.w);
        *(uint4*)(se + row * 68 + k4) = s;
    }
    __syncwarp();

    float c[2][8][4];
#pragma unroll 1
    for (int p = 0; p < 2; p++) {
        zero_c(c);
        warp_gemm(se, p ? sw2 : sw1, gid, tig, c);
        float* outg = p ? g_hx2 : g_hx;
        const float* sb = p ? sb2 : sb1;
#pragma unroll
        for (int mt = 0; mt < 2; mt++) {
            long long r0 = base + mt * 16 + gid;
#pragma unroll
            for (int j = 0; j < 8; j++) {
                float2 bb = *(const float2*)(sb + j * 8 + 2 * tig);
                if (r0 < N)
                    *(float2*)(outg + r0 * 64 + j * 8 + 2 * tig) =
                        make_float2(c[mt][j][0] + bb.x, c[mt][j][1] + bb.y);
                if (r0 + 8 < N)
                    *(float2*)(outg + (r0 + 8) * 64 + j * 8 + 2 * tig) =
                        make_float2(c[mt][j][2] + bb.x, c[mt][j][3] + bb.y);
            }
        }
    }
}

// ================= edge kernel: single GEMM + relu + scatter-add of hidden =================
// h_e = relu(hx[src] + ea@w1a_bot); g_summed[dst] += h_e; count[dst]++
#define ED_SW1 0
#define ED_SE 18432
#define ED_SMEM (ED_SE + 8 * 32 * 68 * 4)  // 88064

__global__ void __launch_bounds__(256, 2) edge_mma_kernel(
    const int* __restrict__ ei, const float* __restrict__ ea,
    const float* __restrict__ w1a,  // rows 64..127 used
    int E, int ntiles) {
    extern __shared__ __align__(16) char dsm[];
    uint32_t* sw1 = (uint32_t*)(dsm + ED_SW1);

    int tid = threadIdx.x;
    int wid = tid >> 5, l = tid & 31;
    int gid = l >> 2, tig = l & 3;
    uint32_t* se = (uint32_t*)(dsm + ED_SE) + wid * 2176;

    for (int idx = tid; idx < 4096; idx += 256) {
        int k = idx >> 6, n = idx & 63;
        sw1[k * 72 + n] = f2tf32(w1a[(64 + k) * 64 + n]);
    }
    __syncthreads();

    for (int tile = blockIdx.x; tile < ntiles; tile += gridDim.x) {
        long long eb = (long long)tile * 256 + wid * 32;
        long long ee = eb + l;
        bool ev = (ee < E);
        int rsrc = ev ? ei[ee] : 0;
        int cdst = ev ? ei[E + ee] : 0;

        __syncwarp();
        // stage ea tile (32 edges x 64) tf32
#pragma unroll
        for (int i = 0; i < 16; i++) {
            int idx = l + 32 * i;
            int row = idx >> 4, k4 = (idx & 15) * 4;
            long long er = eb + row;
            float4 v = (er < E) ? __ldg((const float4*)(ea + er * 64 + k4))
                                : make_float4(0.f, 0.f, 0.f, 0.f);
            uint4 s;
            s.x = f2tf32(v.x); s.y = f2tf32(v.y); s.z = f2tf32(v.z); s.w = f2tf32(v.w);
            *(uint4*)(se + row * 68 + k4) = s;
        }
        __syncwarp();

        float c[2][8][4];
        zero_c(c);
        warp_gemm(se, sw1, gid, tig, c);

        // epilogue: h = relu(C + hx[src]) scatter-added into g_summed[dst]
#pragma unroll
        for (int mt = 0; mt < 2; mt++) {
            int rlo = __shfl_sync(0xffffffffu, rsrc, mt * 16 + gid);
            int rhi = __shfl_sync(0xffffffffu, rsrc, mt * 16 + gid + 8);
            int clo = __shfl_sync(0xffffffffu, cdst, mt * 16 + gid);
            int chi = __shfl_sync(0xffffffffu, cdst, mt * 16 + gid + 8);
            bool vlo = (eb + mt * 16 + gid) < E;
            bool vhi = (eb + mt * 16 + gid + 8) < E;
            const float* hlo = g_hx + (size_t)rlo * DD + 2 * tig;
            const float* hhi = g_hx + (size_t)rhi * DD + 2 * tig;
            float* dlo = g_summed + (size_t)clo * DD + 2 * tig;
            float* dhi = g_summed + (size_t)chi * DD + 2 * tig;
#pragma unroll
            for (int j = 0; j < 8; j++) {
                float2 xl = __ldg((const float2*)(hlo + j * 8));
                float2 xh = __ldg((const float2*)(hhi + j * 8));
                if (vlo) {
                    float f0 = fmaxf(c[mt][j][0] + xl.x, 0.f);
                    float f1 = fmaxf(c[mt][j][1] + xl.y, 0.f);
                    asm volatile("red.global.add.v2.f32 [%0], {%1,%2};"
                                 :: "l"(dlo + j * 8), "f"(f0), "f"(f1) : "memory");
                }
                if (vhi) {
                    float f2 = fmaxf(c[mt][j][2] + xh.x, 0.f);
                    float f3 = fmaxf(c[mt][j][3] + xh.y, 0.f);
                    asm volatile("red.global.add.v2.f32 [%0], {%1,%2};"
                                 :: "l"(dhi + j * 8), "f"(f2), "f"(f3) : "memory");
                }
            }
        }
        if (ev) atomicAdd(&g_counts[cdst], 1.0f);
    }
}

// ================= node kernel: 3-stage chain =================
// hmean = g_summed[n]/max(cnt,1)
// agg   = hmean @ w1b + b1b*(cnt>0)
// h2    = relu(agg @ w2a_bot + hx2[n])
// out   = h2 @ w2b + b2b
#define ND_SW1 0
#define ND_SW2 18432
#define ND_SW3 36864
#define ND_SB1 55296
#define ND_SB2 55552
#define ND_SE 55808
#define ND_SMEM (ND_SE + 8 * 32 * 68 * 4)  // 125440

__global__ void __launch_bounds__(256, 1) node_mma_kernel(
    const float* __restrict__ w1b, const float* __restrict__ b1b,
    const float* __restrict__ w2a,  // rows 64..127 used
    const float* __restrict__ w2b, const float* __restrict__ b2b,
    float* __restrict__ out, int N) {
    extern __shared__ __align__(16) char dsm[];
    uint32_t* sw1 = (uint32_t*)(dsm + ND_SW1);
    uint32_t* sw2 = (uint32_t*)(dsm + ND_SW2);
    uint32_t* sw3 = (uint32_t*)(dsm + ND_SW3);
    float* sb1 = (float*)(dsm + ND_SB1);
    float* sb2 = (float*)(dsm + ND_SB2);

    int tid = threadIdx.x;
    int wid = tid >> 5, l = tid & 31;
    int gid = l >> 2, tig = l & 3;
    uint32_t* se = (uint32_t*)(dsm + ND_SE) + wid * 2176;

    for (int idx = tid; idx < 4096; idx += 256) {
        int k = idx >> 6, n = idx & 63;
        sw1[k * 72 + n] = f2tf32(w1b[k * 64 + n]);
        sw2[k * 72 + n] = f2tf32(w2a[(64 + k) * 64 + n]);
        sw3[k * 72 + n] = f2tf32(w2b[k * 64 + n]);
    }
    if (tid < 64) sb1[tid] = b1b[tid];
    else if (tid < 128) sb2[tid - 64] = b2b[tid - 64];
    __syncthreads();

    long long base = (long long)blockIdx.x * 256 + wid * 32;

    // stage hmean tile as tf32
#pragma unroll
    for (int i = 0; i < 16; i++) {
        int idx = l + 32 * i;
        int row = idx >> 4, k4 = (idx & 15) * 4;
        long long r = base + row;
        float4 v = make_float4(0.f, 0.f, 0.f, 0.f);
        if (r < N) {
            float inv = 1.0f / fmaxf(g_counts[r], 1.0f);
            float4 s = *(const float4*)(g_summed + r * 64 + k4);
            v = make_float4(s.x * inv, s.y * inv, s.z * inv, s.w * inv);
        }
        uint4 s;
        s.x = f2tf32(v.x); s.y = f2tf32(v.y); s.z = f2tf32(v.z); s.w = f2tf32(v.w);
        *(uint4*)(se + row * 68 + k4) = s;
    }
    __syncwarp();

    float c[2][8][4];

    // ---- stage 1: agg = hmean @ w1b^T + b1b*(cnt>0) ----
    zero_c(c);
    warp_gemm(se, sw1, gid, tig, c);
    __syncwarp();
#pragma unroll
    for (int mt = 0; mt < 2; mt++) {
        long long r0 = base + mt * 16 + gid;
        float flo = (r0 < N && g_counts[r0] > 0.f) ? 1.f : 0.f;
        float fhi = (r0 + 8 < N && g_counts[r0 + 8] > 0.f) ? 1.f : 0.f;
        int rr = mt * 16 + gid;
#pragma unroll
        for (int j = 0; j < 8; j++) {
            float2 bb = *(const float2*)(sb1 + j * 8 + 2 * tig);
            uint2 lo, hi;
            lo.x = f2tf32(c[mt][j][0] + flo * bb.x);
            lo.y = f2tf32(c[mt][j][1] + flo * bb.y);
            hi.x = f2tf32(c[mt][j][2] + fhi * bb.x);
            hi.y = f2tf32(c[mt][j][3] + fhi * bb.y);
            *(uint2*)(se + rr * 68 + j * 8 + 2 * tig) = lo;
            *(uint2*)(se + (rr + 8) * 68 + j * 8 + 2 * tig) = hi;
        }
    }
    __syncwarp();

    // ---- stage 2: h2 = relu(agg @ w2a_bot^T + hx2[n]) ----
    zero_c(c);
    warp_gemm(se, sw2, gid, tig, c);
    __syncwarp();
#pragma unroll
    for (int mt = 0; mt < 2; mt++) {
        long long r0 = base + mt * 16 + gid;
        long long rlo = (r0 < N) ? r0 : 0;
        long long rhi = (r0 + 8 < N) ? r0 + 8 : 0;
        const float* hlo = g_hx2 + rlo * DD + 2 * tig;
        const float* hhi = g_hx2 + rhi * DD + 2 * tig;
        int rr = mt * 16 + gid;
#pragma unroll
        for (int j = 0; j < 8; j++) {
            float2 xl = __ldg((const float2*)(hlo + j * 8));
            float2 xh = __ldg((const float2*)(hhi + j * 8));
            uint2 lo, hi;
            lo.x = f2tf32(fmaxf(c[mt][j][0] + xl.x, 0.f));
            lo.y = f2tf32(fmaxf(c[mt][j][1] + xl.y, 0.f));
            hi.x = f2tf32(fmaxf(c[mt][j][2] + xh.x, 0.f));
            hi.y = f2tf32(fmaxf(c[mt][j][3] + xh.y, 0.f));
            *(uint2*)(se + rr * 68 + j * 8 + 2 * tig) = lo;
            *(uint2*)(se + (rr + 8) * 68 + j * 8 + 2 * tig) = hi;
        }
    }
    __syncwarp();

    // ---- stage 3: out = h2 @ w2b^T + b2b ----
    zero_c(c);
    warp_gemm(se, sw3, gid, tig, c);
#pragma unroll
    for (int mt = 0; mt < 2; mt++) {
        long long r0 = base + mt * 16 + gid;
#pragma unroll
        for (int j = 0; j < 8; j++) {
            float2 bb = *(const float2*)(sb2 + j * 8 + 2 * tig);
            if (r0 < N)
                *(float2*)(out + r0 * 64 + j * 8 + 2 * tig) =
                    make_float2(c[mt][j][0] + bb.x, c[mt][j][1] + bb.y);
            if (r0 + 8 < N)
                *(float2*)(out + (r0 + 8) * 64 + j * 8 + 2 * tig) =
                    make_float2(c[mt][j][2] + bb.x, c[mt][j][3] + bb.y);
        }
    }
}

extern "C" void kernel_launch(void* const* d_in, const int* in_sizes, int n_in,
                              void* d_out, int out_size) {
    const float* x   = (const float*)d_in[0];
    const int*   ei  = (const int*)d_in[1];
    const float* ea  = (const float*)d_in[2];
    const float* w1a = (const float*)d_in[5];
    const float* b1a = (const float*)d_in[6];
    const float* w1b = (const float*)d_in[7];
    const float* b1b = (const float*)d_in[8];
    const float* w2a = (const float*)d_in[9];
    const float* b2a = (const float*)d_in[10];
    const float* w2b = (const float*)d_in[11];
    const float* b2b = (const float*)d_in[12];
    float* out = (float*)d_out;

    int N = in_sizes[0] / DD;
    int E = in_sizes[2] / DD;

    cudaFuncSetAttribute(hx_mma_kernel, cudaFuncAttributeMaxDynamicSharedMemorySize, HX_SMEM);
    cudaFuncSetAttribute(edge_mma_kernel, cudaFuncAttributeMaxDynamicSharedMemorySize, ED_SMEM);
    cudaFuncSetAttribute(node_mma_kernel, cudaFuncAttributeMaxDynamicSharedMemorySize, ND_SMEM);

    int ntiles_e = (E + 255) / 256;
    int grid_e = ntiles_e < 296 ? ntiles_e : 296;
    int ntiles_n = (N + 255) / 256;

    zero_summed<<<512, 256>>>(N * DD / 4);
    zero_counts<<<(N + 255) / 256, 256>>>(N);
    hx_mma_kernel<<<ntiles_n, 256, HX_SMEM>>>(x, w1a, b1a, w2a, b2a, N);
    edge_mma_kernel<<<grid_e, 256, ED_SMEM>>>(ei, ea, w1a, E, ntiles_e);
    node_mma_kernel<<<ntiles_n, 256, ND_SMEM>>>(w1b, b1b, w2a, w2b, b2b, out, N);
}

// round 10
// speedup vs baseline: 4.8797x; 1.0242x over previous
#include <cuda_runtime.h>
#include <cuda_bf16.h>
#include <cstdint>

#define MAX_N 50432
#define DD 64

__device__ __align__(16) float g_summed[MAX_N * DD];  // sum of relu(h_e) per dst node
__device__ float g_counts[MAX_N];
__device__ __align__(16) float g_hx[MAX_N * DD];   // x @ w1a[0:64] + b1a
__device__ __align__(16) float g_hx2[MAX_N * DD];  // x @ w2a[0:64] + b2a

// ---------- tf32 + mma helpers ----------
__device__ __forceinline__ uint32_t f2tf32(float f) {
    uint32_t r;
    asm("cvt.rna.tf32.f32 %0, %1;" : "=r"(r) : "f"(f));
    return r;
}
// D(16x8,f32) += A(16x8,tf32,row) * B(8x8,tf32,col)
__device__ __forceinline__ void mma_tf32(float* d, const uint32_t* a,
                                         uint32_t b0, uint32_t b1) {
    asm volatile(
        "mma.sync.aligned.m16n8k8.row.col.f32.tf32.tf32.f32 "
        "{%0,%1,%2,%3}, {%4,%5,%6,%7}, {%8,%9}, {%0,%1,%2,%3};"
        : "+f"(d[0]), "+f"(d[1]), "+f"(d[2]), "+f"(d[3])
        : "r"(a[0]), "r"(a[1]), "r"(a[2]), "r"(a[3]), "r"(b0), "r"(b1));
}

// Warp GEMM: C[32x64] += A(se: 32 rows x 64 k, stride 68) * B(sw: [k][n] stride 72)^T
__device__ __forceinline__ void warp_gemm(const uint32_t* se, const uint32_t* sw,
                                          int gid, int tig, float c[2][8][4]) {
#pragma unroll
    for (int kt = 0; kt < 8; kt++) {
        uint32_t a[2][4];
#pragma unroll
        for (int mt = 0; mt < 2; mt++) {
            int r0 = mt * 16 + gid;
            a[mt][0] = se[r0 * 68 + kt * 8 + tig];
            a[mt][1] = se[(r0 + 8) * 68 + kt * 8 + tig];
            a[mt][2] = se[r0 * 68 + kt * 8 + tig + 4];
            a[mt][3] = se[(r0 + 8) * 68 + kt * 8 + tig + 4];
        }
#pragma unroll
        for (int j = 0; j < 8; j++) {
            uint32_t b0 = sw[(kt * 8 + tig) * 72 + j * 8 + gid];
            uint32_t b1 = sw[(kt * 8 + tig + 4) * 72 + j * 8 + gid];
            mma_tf32(c[0][j], a[0], b0, b1);
            mma_tf32(c[1][j], a[1], b0, b1);
        }
    }
}

__device__ __forceinline__ void zero_c(float c[2][8][4]) {
#pragma unroll
    for (int mt = 0; mt < 2; mt++)
#pragma unroll
        for (int j = 0; j < 8; j++)
#pragma unroll
            for (int r = 0; r < 4; r++) c[mt][j][r] = 0.f;
}

// ---------- zero scratch ----------
__global__ void zero_summed(int n_f4) {
    int i = blockIdx.x * blockDim.x + threadIdx.x;
    int stride = gridDim.x * blockDim.x;
    float4 z = make_float4(0.f, 0.f, 0.f, 0.f);
    for (int j = i; j < n_f4; j += stride) ((float4*)g_summed)[j] = z;
}
__global__ void zero_counts(int n) {
    int i = blockIdx.x * blockDim.x + threadIdx.x;
    if (i < n) g_counts[i] = 0.f;
}

// ================= hx kernel: hx = x@w1a_top + b1a, hx2 = x@w2a_top + b2a =================
#define HX_SW1 0
#define HX_SW2 18432
#define HX_SB 36864
#define HX_SB2 37120
#define HX_SE 37376
#define HX_SMEM (HX_SE + 8 * 32 * 68 * 4)  // 107008

__global__ void __launch_bounds__(256, 2) hx_mma_kernel(
    const float* __restrict__ x,
    const float* __restrict__ w1a, const float* __restrict__ b1a,
    const float* __restrict__ w2a, const float* __restrict__ b2a,
    int N) {
    extern __shared__ __align__(16) char dsm[];
    uint32_t* sw1 = (uint32_t*)(dsm + HX_SW1);
    uint32_t* sw2 = (uint32_t*)(dsm + HX_SW2);
    float* sb1 = (float*)(dsm + HX_SB);
    float* sb2 = (float*)(dsm + HX_SB2);

    int tid = threadIdx.x;
    int wid = tid >> 5, l = tid & 31;
    int gid = l >> 2, tig = l & 3;
    uint32_t* se = (uint32_t*)(dsm + HX_SE) + wid * 2176;

    for (int idx = tid; idx < 4096; idx += 256) {
        int k = idx >> 6, n = idx & 63;
        sw1[k * 72 + n] = f2tf32(w1a[k * 64 + n]);  // top rows 0..63
        sw2[k * 72 + n] = f2tf32(w2a[k * 64 + n]);
    }
    if (tid < 64) sb1[tid] = b1a[tid];
    else if (tid < 128) sb2[tid - 64] = b2a[tid - 64];
    __syncthreads();

    long long base = (long long)blockIdx.x * 256 + wid * 32;

#pragma unroll
    for (int i = 0; i < 16; i++) {
        int idx = l + 32 * i;
        int row = idx >> 4, k4 = (idx & 15) * 4;
        long long r = base + row;
        float4 v = (r < N) ? __ldg((const float4*)(x + r * 64 + k4))
                           : make_float4(0.f, 0.f, 0.f, 0.f);
        uint4 s;
        s.x = f2tf32(v.x); s.y = f2tf32(v.y); s.z = f2tf32(v.z); s.w = f2tf32(v.w);
        *(uint4*)(se + row * 68 + k4) = s;
    }
    __syncwarp();

    float c[2][8][4];
#pragma unroll 1
    for (int p = 0; p < 2; p++) {
        zero_c(c);
        warp_gemm(se, p ? sw2 : sw1, gid, tig, c);
        float* outg = p ? g_hx2 : g_hx;
        const float* sb = p ? sb2 : sb1;
#pragma unroll
        for (int mt = 0; mt < 2; mt++) {
            long long r0 = base + mt * 16 + gid;
#pragma unroll
            for (int j = 0; j < 8; j++) {
                float2 bb = *(const float2*)(sb + j * 8 + 2 * tig);
                if (r0 < N)
                    *(float2*)(outg + r0 * 64 + j * 8 + 2 * tig) =
                        make_float2(c[mt][j][0] + bb.x, c[mt][j][1] + bb.y);
                if (r0 + 8 < N)
                    *(float2*)(outg + (r0 + 8) * 64 + j * 8 + 2 * tig) =
                        make_float2(c[mt][j][2] + bb.x, c[mt][j][3] + bb.y);
            }
        }
    }
}

// ================= edge kernel: single GEMM + relu + row-major scatter-add =================
// h_e = relu(hx[src] + ea@w1a_bot); g_summed[dst] += h_e; count[dst]++
#define ED_SW1 0
#define ED_SE 18432
#define ED_SMEM (ED_SE + 8 * 32 * 68 * 4)  // 88064

__global__ void __launch_bounds__(256, 2) edge_mma_kernel(
    const int* __restrict__ ei, const float* __restrict__ ea,
    const float* __restrict__ w1a,  // rows 64..127 used
    int E, int ntiles) {
    extern __shared__ __align__(16) char dsm[];
    uint32_t* sw1 = (uint32_t*)(dsm + ED_SW1);

    int tid = threadIdx.x;
    int wid = tid >> 5, l = tid & 31;
    int gid = l >> 2, tig = l & 3;
    uint32_t* se = (uint32_t*)(dsm + ED_SE) + wid * 2176;
    float* sef = (float*)se;

    for (int idx = tid; idx < 4096; idx += 256) {
        int k = idx >> 6, n = idx & 63;
        sw1[k * 72 + n] = f2tf32(w1a[(64 + k) * 64 + n]);
    }
    __syncthreads();

    int half = l >> 4;   // 0..1 : which row of the pair
    int qc = l & 15;     // float4 chunk within a row

    for (int tile = blockIdx.x; tile < ntiles; tile += gridDim.x) {
        long long eb = (long long)tile * 256 + wid * 32;
        long long ee = eb + l;
        bool ev = (ee < E);
        int rsrc = ev ? ei[ee] : 0;
        int cdst = ev ? ei[E + ee] : 0;

        __syncwarp();
        // stage ea tile (32 edges x 64) tf32
#pragma unroll
        for (int i = 0; i < 16; i++) {
            int idx = l + 32 * i;
            int row = idx >> 4, k4 = (idx & 15) * 4;
            long long er = eb + row;
            float4 v = (er < E) ? __ldg((const float4*)(ea + er * 64 + k4))
                                : make_float4(0.f, 0.f, 0.f, 0.f);
            uint4 s;
            s.x = f2tf32(v.x); s.y = f2tf32(v.y); s.z = f2tf32(v.z); s.w = f2tf32(v.w);
            *(uint4*)(se + row * 68 + k4) = s;
        }
        __syncwarp();

        float c[2][8][4];
        zero_c(c);
        warp_gemm(se, sw1, gid, tig, c);
        __syncwarp();

        // transpose C into smem tile (fragment-layout stores)
#pragma unroll
        for (int mt = 0; mt < 2; mt++) {
            int r0 = mt * 16 + gid;
#pragma unroll
            for (int j = 0; j < 8; j++) {
                *(float2*)(sef + r0 * 68 + j * 8 + 2 * tig) =
                    make_float2(c[mt][j][0], c[mt][j][1]);
                *(float2*)(sef + (r0 + 8) * 68 + j * 8 + 2 * tig) =
                    make_float2(c[mt][j][2], c[mt][j][3]);
            }
        }
        __syncwarp();

        // row-major epilogue: 2 edge-rows per iteration, 16 lanes per row.
        // gather hx[src] coalesced (2 full 256B rows / instr), relu, red.v4 scatter.
#pragma unroll
        for (int i = 0; i < 16; i++) {
            int row = 2 * i + half;
            int src = __shfl_sync(0xffffffffu, rsrc, row);
            int dst = __shfl_sync(0xffffffffu, cdst, row);
            bool v = (eb + row) < E;
            float4 cv = *(const float4*)(sef + row * 68 + qc * 4);
            float4 hv = __ldg((const float4*)(g_hx + (size_t)src * DD + qc * 4));
            if (v) {
                float f0 = fmaxf(cv.x + hv.x, 0.f);
                float f1 = fmaxf(cv.y + hv.y, 0.f);
                float f2 = fmaxf(cv.z + hv.z, 0.f);
                float f3 = fmaxf(cv.w + hv.w, 0.f);
                asm volatile("red.global.add.v4.f32 [%0], {%1,%2,%3,%4};"
                             :: "l"(g_summed + (size_t)dst * DD + qc * 4),
                                "f"(f0), "f"(f1), "f"(f2), "f"(f3)
                             : "memory");
            }
        }
        if (ev) atomicAdd(&g_counts[cdst], 1.0f);
    }
}

// ================= node kernel: 3-stage chain =================
// hmean = g_summed[n]/max(cnt,1)
// agg   = hmean @ w1b + b1b*(cnt>0)
// h2    = relu(agg @ w2a_bot + hx2[n])
// out   = h2 @ w2b + b2b
#define ND_SW1 0
#define ND_SW2 18432
#define ND_SW3 36864
#define ND_SB1 55296
#define ND_SB2 55552
#define ND_SE 55808
#define ND_SMEM (ND_SE + 8 * 32 * 68 * 4)  // 125440

__global__ void __launch_bounds__(256, 1) node_mma_kernel(
    const float* __restrict__ w1b, const float* __restrict__ b1b,
    const float* __restrict__ w2a,  // rows 64..127 used
    const float* __restrict__ w2b, const float* __restrict__ b2b,
    float* __restrict__ out, int N) {
    extern __shared__ __align__(16) char dsm[];
    uint32_t* sw1 = (uint32_t*)(dsm + ND_SW1);
    uint32_t* sw2 = (uint32_t*)(dsm + ND_SW2);
    uint32_t* sw3 = (uint32_t*)(dsm + ND_SW3);
    float* sb1 = (float*)(dsm + ND_SB1);
    float* sb2 = (float*)(dsm + ND_SB2);

    int tid = threadIdx.x;
    int wid = tid >> 5, l = tid & 31;
    int gid = l >> 2, tig = l & 3;
    uint32_t* se = (uint32_t*)(dsm + ND_SE) + wid * 2176;

    for (int idx = tid; idx < 4096; idx += 256) {
        int k = idx >> 6, n = idx & 63;
        sw1[k * 72 + n] = f2tf32(w1b[k * 64 + n]);
        sw2[k * 72 + n] = f2tf32(w2a[(64 + k) * 64 + n]);
        sw3[k * 72 + n] = f2tf32(w2b[k * 64 + n]);
    }
    if (tid < 64) sb1[tid] = b1b[tid];
    else if (tid < 128) sb2[tid - 64] = b2b[tid - 64];
    __syncthreads();

    long long base = (long long)blockIdx.x * 256 + wid * 32;

    // stage hmean tile as tf32
#pragma unroll
    for (int i = 0; i < 16; i++) {
        int idx = l + 32 * i;
        int row = idx >> 4, k4 = (idx & 15) * 4;
        long long r = base + row;
        float4 v = make_float4(0.f, 0.f, 0.f, 0.f);
        if (r < N) {
            float inv = 1.0f / fmaxf(g_counts[r], 1.0f);
            float4 s = *(const float4*)(g_summed + r * 64 + k4);
            v = make_float4(s.x * inv, s.y * inv, s.z * inv, s.w * inv);
        }
        uint4 s;
        s.x = f2tf32(v.x); s.y = f2tf32(v.y); s.z = f2tf32(v.z); s.w = f2tf32(v.w);
        *(uint4*)(se + row * 68 + k4) = s;
    }
    __syncwarp();

    float c[2][8][4];

    // ---- stage 1: agg = hmean @ w1b^T + b1b*(cnt>0) ----
    zero_c(c);
    warp_gemm(se, sw1, gid, tig, c);
    __syncwarp();
#pragma unroll
    for (int mt = 0; mt < 2; mt++) {
        long long r0 = base + mt * 16 + gid;
        float flo = (r0 < N && g_counts[r0] > 0.f) ? 1.f : 0.f;
        float fhi = (r0 + 8 < N && g_counts[r0 + 8] > 0.f) ? 1.f : 0.f;
        int rr = mt * 16 + gid;
#pragma unroll
        for (int j = 0; j < 8; j++) {
            float2 bb = *(const float2*)(sb1 + j * 8 + 2 * tig);
            uint2 lo, hi;
            lo.x = f2tf32(c[mt][j][0] + flo * bb.x);
            lo.y = f2tf32(c[mt][j][1] + flo * bb.y);
            hi.x = f2tf32(c[mt][j][2] + fhi * bb.x);
            hi.y = f2tf32(c[mt][j][3] + fhi * bb.y);
            *(uint2*)(se + rr * 68 + j * 8 + 2 * tig) = lo;
            *(uint2*)(se + (rr + 8) * 68 + j * 8 + 2 * tig) = hi;
        }
    }
    __syncwarp();

    // ---- stage 2: h2 = relu(agg @ w2a_bot^T + hx2[n]) ----
    zero_c(c);
    warp_gemm(se, sw2, gid, tig, c);
    __syncwarp();
#pragma unroll
    for (int mt = 0; mt < 2; mt++) {
        long long r0 = base + mt * 16 + gid;
        long long rlo = (r0 < N) ? r0 : 0;
        long long rhi = (r0 + 8 < N) ? r0 + 8 : 0;
        const float* hlo = g_hx2 + rlo * DD + 2 * tig;
        const float* hhi = g_hx2 + rhi * DD + 2 * tig;
        int rr = mt * 16 + gid;
#pragma unroll
        for (int j = 0; j < 8; j++) {
            float2 xl = __ldg((const float2*)(hlo + j * 8));
            float2 xh = __ldg((const float2*)(hhi + j * 8));
            uint2 lo, hi;
            lo.x = f2tf32(fmaxf(c[mt][j][0] + xl.x, 0.f));
            lo.y = f2tf32(fmaxf(c[mt][j][1] + xl.y, 0.f));
            hi.x = f2tf32(fmaxf(c[mt][j][2] + xh.x, 0.f));
            hi.y = f2tf32(fmaxf(c[mt][j][3] + xh.y, 0.f));
            *(uint2*)(se + rr * 68 + j * 8 + 2 * tig) = lo;
            *(uint2*)(se + (rr + 8) * 68 + j * 8 + 2 * tig) = hi;
        }
    }
    __syncwarp();

    // ---- stage 3: out = h2 @ w2b^T + b2b ----
    zero_c(c);
    warp_gemm(se, sw3, gid, tig, c);
#pragma unroll
    for (int mt = 0; mt < 2; mt++) {
        long long r0 = base + mt * 16 + gid;
#pragma unroll
        for (int j = 0; j < 8; j++) {
            float2 bb = *(const float2*)(sb2 + j * 8 + 2 * tig);
            if (r0 < N)
                *(float2*)(out + r0 * 64 + j * 8 + 2 * tig) =
                    make_float2(c[mt][j][0] + bb.x, c[mt][j][1] + bb.y);
            if (r0 + 8 < N)
                *(float2*)(out + (r0 + 8) * 64 + j * 8 + 2 * tig) =
                    make_float2(c[mt][j][2] + bb.x, c[mt][j][3] + bb.y);
        }
    }
}

extern "C" void kernel_launch(void* const* d_in, const int* in_sizes, int n_in,
                              void* d_out, int out_size) {
    const float* x   = (const float*)d_in[0];
    const int*   ei  = (const int*)d_in[1];
    const float* ea  = (const float*)d_in[2];
    const float* w1a = (const float*)d_in[5];
    const float* b1a = (const float*)d_in[6];
    const float* w1b = (const float*)d_in[7];
    const float* b1b = (const float*)d_in[8];
    const float* w2a = (const float*)d_in[9];
    const float* b2a = (const float*)d_in[10];
    const float* w2b = (const float*)d_in[11];
    const float* b2b = (const float*)d_in[12];
    float* out = (float*)d_out;

    int N = in_sizes[0] / DD;
    int E = in_sizes[2] / DD;

    cudaFuncSetAttribute(hx_mma_kernel, cudaFuncAttributeMaxDynamicSharedMemorySize, HX_SMEM);
    cudaFuncSetAttribute(edge_mma_kernel, cudaFuncAttributeMaxDynamicSharedMemorySize, ED_SMEM);
    cudaFuncSetAttribute(node_mma_kernel, cudaFuncAttributeMaxDynamicSharedMemorySize, ND_SMEM);

    int ntiles_e = (E + 255) / 256;
    int grid_e = ntiles_e < 296 ? ntiles_e : 296;
    int ntiles_n = (N + 255) / 256;

    zero_summed<<<512, 256>>>(N * DD / 4);
    zero_counts<<<(N + 255) / 256, 256>>>(N);
    hx_mma_kernel<<<ntiles_n, 256, HX_SMEM>>>(x, w1a, b1a, w2a, b2a, N);
    edge_mma_kernel<<<grid_e, 256, ED_SMEM>>>(ei, ea, w1a, E, ntiles_e);
    node_mma_kernel<<<ntiles_n, 256, ND_SMEM>>>(w1b, b1b, w2a, w2b, b2b, out, N);
}

// round 11
// speedup vs baseline: 4.9151x; 1.0073x over previous
#include <cuda_runtime.h>
#include <cuda_bf16.h>
#include <cstdint>

#define MAX_N 50432
#define DD 64

__device__ __align__(16) float g_summed[MAX_N * DD];  // sum of relu(h_e) per dst node
__device__ float g_counts[MAX_N];
__device__ __align__(16) float g_hx[MAX_N * DD];   // x @ w1a[0:64] + b1a
__device__ __align__(16) float g_hx2[MAX_N * DD];  // x @ w2a[0:64] + b2a

// ---------- tf32 + mma helpers ----------
__device__ __forceinline__ uint32_t f2tf32(float f) {
    uint32_t r;
    asm("cvt.rna.tf32.f32 %0, %1;" : "=r"(r) : "f"(f));
    return r;
}
// D(16x8,f32) += A(16x8,tf32,row) * B(8x8,tf32,col)
__device__ __forceinline__ void mma_tf32(float* d, const uint32_t* a,
                                         uint32_t b0, uint32_t b1) {
    asm volatile(
        "mma.sync.aligned.m16n8k8.row.col.f32.tf32.tf32.f32 "
        "{%0,%1,%2,%3}, {%4,%5,%6,%7}, {%8,%9}, {%0,%1,%2,%3};"
        : "+f"(d[0]), "+f"(d[1]), "+f"(d[2]), "+f"(d[3])
        : "r"(a[0]), "r"(a[1]), "r"(a[2]), "r"(a[3]), "r"(b0), "r"(b1));
}

// Warp GEMM: C[32x64] += A(se: 32 rows x 64 k, stride 68) * B(sw: [k][n] stride 72)^T
__device__ __forceinline__ void warp_gemm(const uint32_t* se, const uint32_t* sw,
                                          int gid, int tig, float c[2][8][4]) {
#pragma unroll
    for (int kt = 0; kt < 8; kt++) {
        uint32_t a[2][4];
#pragma unroll
        for (int mt = 0; mt < 2; mt++) {
            int r0 = mt * 16 + gid;
            a[mt][0] = se[r0 * 68 + kt * 8 + tig];
            a[mt][1] = se[(r0 + 8) * 68 + kt * 8 + tig];
            a[mt][2] = se[r0 * 68 + kt * 8 + tig + 4];
            a[mt][3] = se[(r0 + 8) * 68 + kt * 8 + tig + 4];
        }
#pragma unroll
        for (int j = 0; j < 8; j++) {
            uint32_t b0 = sw[(kt * 8 + tig) * 72 + j * 8 + gid];
            uint32_t b1 = sw[(kt * 8 + tig + 4) * 72 + j * 8 + gid];
            mma_tf32(c[0][j], a[0], b0, b1);
            mma_tf32(c[1][j], a[1], b0, b1);
        }
    }
}

__device__ __forceinline__ void zero_c(float c[2][8][4]) {
#pragma unroll
    for (int mt = 0; mt < 2; mt++)
#pragma unroll
        for (int j = 0; j < 8; j++)
#pragma unroll
            for (int r = 0; r < 4; r++) c[mt][j][r] = 0.f;
}

// ---------- zero scratch ----------
__global__ void zero_summed(int n_f4) {
    int i = blockIdx.x * blockDim.x + threadIdx.x;
    int stride = gridDim.x * blockDim.x;
    float4 z = make_float4(0.f, 0.f, 0.f, 0.f);
    for (int j = i; j < n_f4; j += stride) ((float4*)g_summed)[j] = z;
}
__global__ void zero_counts(int n) {
    int i = blockIdx.x * blockDim.x + threadIdx.x;
    if (i < n) g_counts[i] = 0.f;
}

// ================= hx kernel: hx = x@w1a_top + b1a, hx2 = x@w2a_top + b2a =================
#define HX_SW1 0
#define HX_SW2 18432
#define HX_SB 36864
#define HX_SB2 37120
#define HX_SE 37376
#define HX_SMEM (HX_SE + 8 * 32 * 68 * 4)  // 107008

__global__ void __launch_bounds__(256, 2) hx_mma_kernel(
    const float* __restrict__ x,
    const float* __restrict__ w1a, const float* __restrict__ b1a,
    const float* __restrict__ w2a, const float* __restrict__ b2a,
    int N) {
    extern __shared__ __align__(16) char dsm[];
    uint32_t* sw1 = (uint32_t*)(dsm + HX_SW1);
    uint32_t* sw2 = (uint32_t*)(dsm + HX_SW2);
    float* sb1 = (float*)(dsm + HX_SB);
    float* sb2 = (float*)(dsm + HX_SB2);

    int tid = threadIdx.x;
    int wid = tid >> 5, l = tid & 31;
    int gid = l >> 2, tig = l & 3;
    uint32_t* se = (uint32_t*)(dsm + HX_SE) + wid * 2176;

    for (int idx = tid; idx < 4096; idx += 256) {
        int k = idx >> 6, n = idx & 63;
        sw1[k * 72 + n] = f2tf32(w1a[k * 64 + n]);  // top rows 0..63
        sw2[k * 72 + n] = f2tf32(w2a[k * 64 + n]);
    }
    if (tid < 64) sb1[tid] = b1a[tid];
    else if (tid < 128) sb2[tid - 64] = b2a[tid - 64];
    __syncthreads();

    long long base = (long long)blockIdx.x * 256 + wid * 32;

#pragma unroll
    for (int i = 0; i < 16; i++) {
        int idx = l + 32 * i;
        int row = idx >> 4, k4 = (idx & 15) * 4;
        long long r = base + row;
        float4 v = (r < N) ? __ldg((const float4*)(x + r * 64 + k4))
                           : make_float4(0.f, 0.f, 0.f, 0.f);
        uint4 s;
        s.x = f2tf32(v.x); s.y = f2tf32(v.y); s.z = f2tf32(v.z); s.w = f2tf32(v.w);
        *(uint4*)(se + row * 68 + k4) = s;
    }
    __syncwarp();

    float c[2][8][4];
#pragma unroll 1
    for (int p = 0; p < 2; p++) {
        zero_c(c);
        warp_gemm(se, p ? sw2 : sw1, gid, tig, c);
        float* outg = p ? g_hx2 : g_hx;
        const float* sb = p ? sb2 : sb1;
#pragma unroll
        for (int mt = 0; mt < 2; mt++) {
            long long r0 = base + mt * 16 + gid;
#pragma unroll
            for (int j = 0; j < 8; j++) {
                float2 bb = *(const float2*)(sb + j * 8 + 2 * tig);
                if (r0 < N)
                    *(float2*)(outg + r0 * 64 + j * 8 + 2 * tig) =
                        make_float2(c[mt][j][0] + bb.x, c[mt][j][1] + bb.y);
                if (r0 + 8 < N)
                    *(float2*)(outg + (r0 + 8) * 64 + j * 8 + 2 * tig) =
                        make_float2(c[mt][j][2] + bb.x, c[mt][j][3] + bb.y);
            }
        }
    }
}

// ================= edge kernel: single GEMM + relu + row-major scatter-add =================
// h_e = relu(hx[src] + ea@w1a_bot); g_summed[dst] += h_e; count[dst]++
#define ED_SW1 0
#define ED_SE 18432
#define ED_SMEM (ED_SE + 8 * 32 * 68 * 4)  // 88064

__global__ void __launch_bounds__(256, 2) edge_mma_kernel(
    const int* __restrict__ ei, const float* __restrict__ ea,
    const float* __restrict__ w1a,  // rows 64..127 used
    int E, int ntiles) {
    extern __shared__ __align__(16) char dsm[];
    uint32_t* sw1 = (uint32_t*)(dsm + ED_SW1);

    int tid = threadIdx.x;
    int wid = tid >> 5, l = tid & 31;
    int gid = l >> 2, tig = l & 3;
    uint32_t* se = (uint32_t*)(dsm + ED_SE) + wid * 2176;
    float* sef = (float*)se;

    for (int idx = tid; idx < 4096; idx += 256) {
        int k = idx >> 6, n = idx & 63;
        sw1[k * 72 + n] = f2tf32(w1a[(64 + k) * 64 + n]);
    }
    __syncthreads();

    int half = l >> 4;   // 0..1 : which row of the pair
    int qc = l & 15;     // float4 chunk within a row

    for (int tile = blockIdx.x; tile < ntiles; tile += gridDim.x) {
        long long eb = (long long)tile * 256 + wid * 32;
        long long ee = eb + l;
        bool ev = (ee < E);
        int rsrc = ev ? ei[ee] : 0;
        int cdst = ev ? ei[E + ee] : 0;

        __syncwarp();
        // stage ea tile (32 edges x 64) tf32
#pragma unroll
        for (int i = 0; i < 16; i++) {
            int idx = l + 32 * i;
            int row = idx >> 4, k4 = (idx & 15) * 4;
            long long er = eb + row;
            float4 v = (er < E) ? __ldg((const float4*)(ea + er * 64 + k4))
                                : make_float4(0.f, 0.f, 0.f, 0.f);
            uint4 s;
            s.x = f2tf32(v.x); s.y = f2tf32(v.y); s.z = f2tf32(v.z); s.w = f2tf32(v.w);
            *(uint4*)(se + row * 68 + k4) = s;
        }
        __syncwarp();

        float c[2][8][4];
        zero_c(c);
        warp_gemm(se, sw1, gid, tig, c);
        __syncwarp();

        // transpose C into smem tile (fragment-layout stores)
#pragma unroll
        for (int mt = 0; mt < 2; mt++) {
            int r0 = mt * 16 + gid;
#pragma unroll
            for (int j = 0; j < 8; j++) {
                *(float2*)(sef + r0 * 68 + j * 8 + 2 * tig) =
                    make_float2(c[mt][j][0], c[mt][j][1]);
                *(float2*)(sef + (r0 + 8) * 68 + j * 8 + 2 * tig) =
                    make_float2(c[mt][j][2], c[mt][j][3]);
            }
        }
        __syncwarp();

        // row-major epilogue: 2 edge-rows per iteration, 16 lanes per row.
        // gather hx[src] coalesced (2 full 256B rows / instr), relu, red.v4 scatter.
#pragma unroll
        for (int i = 0; i < 16; i++) {
            int row = 2 * i + half;
            int src = __shfl_sync(0xffffffffu, rsrc, row);
            int dst = __shfl_sync(0xffffffffu, cdst, row);
            bool v = (eb + row) < E;
            float4 cv = *(const float4*)(sef + row * 68 + qc * 4);
            float4 hv = __ldg((const float4*)(g_hx + (size_t)src * DD + qc * 4));
            if (v) {
                float f0 = fmaxf(cv.x + hv.x, 0.f);
                float f1 = fmaxf(cv.y + hv.y, 0.f);
                float f2 = fmaxf(cv.z + hv.z, 0.f);
                float f3 = fmaxf(cv.w + hv.w, 0.f);
                asm volatile("red.global.add.v4.f32 [%0], {%1,%2,%3,%4};"
                             :: "l"(g_summed + (size_t)dst * DD + qc * 4),
                                "f"(f0), "f"(f1), "f"(f2), "f"(f3)
                             : "memory");
            }
        }
        if (ev) atomicAdd(&g_counts[cdst], 1.0f);
    }
}

// ================= node kernel: 3-stage chain =================
// hmean = g_summed[n]/max(cnt,1)
// agg   = hmean @ w1b + b1b*(cnt>0)
// h2    = relu(agg @ w2a_bot + hx2[n])
// out   = h2 @ w2b + b2b
#define ND_SW1 0
#define ND_SW2 18432
#define ND_SW3 36864
#define ND_SB1 55296
#define ND_SB2 55552
#define ND_SE 55808
#define ND_SMEM (ND_SE + 8 * 32 * 68 * 4)  // 125440

__global__ void __launch_bounds__(256, 1) node_mma_kernel(
    const float* __restrict__ w1b, const float* __restrict__ b1b,
    const float* __restrict__ w2a,  // rows 64..127 used
    const float* __restrict__ w2b, const float* __restrict__ b2b,
    float* __restrict__ out, int N) {
    extern __shared__ __align__(16) char dsm[];
    uint32_t* sw1 = (uint32_t*)(dsm + ND_SW1);
    uint32_t* sw2 = (uint32_t*)(dsm + ND_SW2);
    uint32_t* sw3 = (uint32_t*)(dsm + ND_SW3);
    float* sb1 = (float*)(dsm + ND_SB1);
    float* sb2 = (float*)(dsm + ND_SB2);

    int tid = threadIdx.x;
    int wid = tid >> 5, l = tid & 31;
    int gid = l >> 2, tig = l & 3;
    uint32_t* se = (uint32_t*)(dsm + ND_SE) + wid * 2176;

    for (int idx = tid; idx < 4096; idx += 256) {
        int k = idx >> 6, n = idx & 63;
        sw1[k * 72 + n] = f2tf32(w1b[k * 64 + n]);
        sw2[k * 72 + n] = f2tf32(w2a[(64 + k) * 64 + n]);
        sw3[k * 72 + n] = f2tf32(w2b[k * 64 + n]);
    }
    if (tid < 64) sb1[tid] = b1b[tid];
    else if (tid < 128) sb2[tid - 64] = b2b[tid - 64];
    __syncthreads();

    long long base = (long long)blockIdx.x * 256 + wid * 32;

    // stage hmean tile as tf32
#pragma unroll
    for (int i = 0; i < 16; i++) {
        int idx = l + 32 * i;
        int row = idx >> 4, k4 = (idx & 15) * 4;
        long long r = base + row;
        float4 v = make_float4(0.f, 0.f, 0.f, 0.f);
        if (r < N) {
            float inv = 1.0f / fmaxf(g_counts[r], 1.0f);
            float4 s = *(const float4*)(g_summed + r * 64 + k4);
            v = make_float4(s.x * inv, s.y * inv, s.z * inv, s.w * inv);
        }
        uint4 s;
        s.x = f2tf32(v.x); s.y = f2tf32(v.y); s.z = f2tf32(v.z); s.w = f2tf32(v.w);
        *(uint4*)(se + row * 68 + k4) = s;
    }
    __syncwarp();

    float c[2][8][4];

    // ---- stage 1: agg = hmean @ w1b^T + b1b*(cnt>0) ----
    zero_c(c);
    warp_gemm(se, sw1, gid, tig, c);
    __syncwarp();
#pragma unroll
    for (int mt = 0; mt < 2; mt++) {
        long long r0 = base + mt * 16 + gid;
        float flo = (r0 < N && g_counts[r0] > 0.f) ? 1.f : 0.f;
        float fhi = (r0 + 8 < N && g_counts[r0 + 8] > 0.f) ? 1.f : 0.f;
        int rr = mt * 16 + gid;
#pragma unroll
        for (int j = 0; j < 8; j++) {
            float2 bb = *(const float2*)(sb1 + j * 8 + 2 * tig);
            uint2 lo, hi;
            lo.x = f2tf32(c[mt][j][0] + flo * bb.x);
            lo.y = f2tf32(c[mt][j][1] + flo * bb.y);
            hi.x = f2tf32(c[mt][j][2] + fhi * bb.x);
            hi.y = f2tf32(c[mt][j][3] + fhi * bb.y);
            *(uint2*)(se + rr * 68 + j * 8 + 2 * tig) = lo;
            *(uint2*)(se + (rr + 8) * 68 + j * 8 + 2 * tig) = hi;
        }
    }
    __syncwarp();

    // ---- stage 2: h2 = relu(agg @ w2a_bot^T + hx2[n]) ----
    zero_c(c);
    warp_gemm(se, sw2, gid, tig, c);
    __syncwarp();
#pragma unroll
    for (int mt = 0; mt < 2; mt++) {
        long long r0 = base + mt * 16 + gid;
        long long rlo = (r0 < N) ? r0 : 0;
        long long rhi = (r0 + 8 < N) ? r0 + 8 : 0;
        const float* hlo = g_hx2 + rlo * DD + 2 * tig;
        const float* hhi = g_hx2 + rhi * DD + 2 * tig;
        int rr = mt * 16 + gid;
#pragma unroll
        for (int j = 0; j < 8; j++) {
            float2 xl = __ldg((const float2*)(hlo + j * 8));
            float2 xh = __ldg((const float2*)(hhi + j * 8));
            uint2 lo, hi;
            lo.x = f2tf32(fmaxf(c[mt][j][0] + xl.x, 0.f));
            lo.y = f2tf32(fmaxf(c[mt][j][1] + xl.y, 0.f));
            hi.x = f2tf32(fmaxf(c[mt][j][2] + xh.x, 0.f));
            hi.y = f2tf32(fmaxf(c[mt][j][3] + xh.y, 0.f));
            *(uint2*)(se + rr * 68 + j * 8 + 2 * tig) = lo;
            *(uint2*)(se + (rr + 8) * 68 + j * 8 + 2 * tig) = hi;
        }
    }
    __syncwarp();

    // ---- stage 3: out = h2 @ w2b^T + b2b ----
    zero_c(c);
    warp_gemm(se, sw3, gid, tig, c);
#pragma unroll
    for (int mt = 0; mt < 2; mt++) {
        long long r0 = base + mt * 16 + gid;
#pragma unroll
        for (int j = 0; j < 8; j++) {
            float2 bb = *(const float2*)(sb2 + j * 8 + 2 * tig);
            if (r0 < N)
                *(float2*)(out + r0 * 64 + j * 8 + 2 * tig) =
                    make_float2(c[mt][j][0] + bb.x, c[mt][j][1] + bb.y);
            if (r0 + 8 < N)
                *(float2*)(out + (r0 + 8) * 64 + j * 8 + 2 * tig) =
                    make_float2(c[mt][j][2] + bb.x, c[mt][j][3] + bb.y);
        }
    }
}

extern "C" void kernel_launch(void* const* d_in, const int* in_sizes, int n_in,
                              void* d_out, int out_size) {
    const float* x   = (const float*)d_in[0];
    const int*   ei  = (const int*)d_in[1];
    const float* ea  = (const float*)d_in[2];
    const float* w1a = (const float*)d_in[5];
    const float* b1a = (const float*)d_in[6];
    const float* w1b = (const float*)d_in[7];
    const float* b1b = (const float*)d_in[8];
    const float* w2a = (const float*)d_in[9];
    const float* b2a = (const float*)d_in[10];
    const float* w2b = (const float*)d_in[11];
    const float* b2b = (const float*)d_in[12];
    float* out = (float*)d_out;

    int N = in_sizes[0] / DD;
    int E = in_sizes[2] / DD;

    cudaFuncSetAttribute(hx_mma_kernel, cudaFuncAttributeMaxDynamicSharedMemorySize, HX_SMEM);
    cudaFuncSetAttribute(edge_mma_kernel, cudaFuncAttributeMaxDynamicSharedMemorySize, ED_SMEM);
    cudaFuncSetAttribute(node_mma_kernel, cudaFuncAttributeMaxDynamicSharedMemorySize, ND_SMEM);

    int ntiles_e = (E + 255) / 256;
    int grid_e = ntiles_e < 296 ? ntiles_e : 296;
    int ntiles_n = (N + 255) / 256;

    zero_summed<<<512, 256>>>(N * DD / 4);
    zero_counts<<<(N + 255) / 256, 256>>>(N);
    hx_mma_kernel<<<ntiles_n, 256, HX_SMEM>>>(x, w1a, b1a, w2a, b2a, N);
    edge_mma_kernel<<<grid_e, 256, ED_SMEM>>>(ei, ea, w1a, E, ntiles_e);
    node_mma_kernel<<<ntiles_n, 256, ND_SMEM>>>(w1b, b1b, w2a, w2b, b2b, out, N);
}